// round 4
// baseline (speedup 1.0000x reference)
#include <cuda_runtime.h>

// Problem constants (fixed by reference)
#define BATCH   1000
#define NUE_    4
#define K_      500
#define M_      500
#define N_      1000
#define NSYM_   250
#define NEDGE_  2000
#define NINFOE_ 1500
#define NITER_  5

// Global CSR (built once per call by setup kernel)
__device__ short g_eoff[M_ + 1];
__device__ short g_elist[NINFOE_];

// Dynamic shared layout (bytes):
//  sL    float4[N_]       16000
//  sC    float4[NINFOE_]  24000
//  sT    float4[NEDGE_]   32000
//  bits  uchar [4*N_]      4000
//  selist short[NINFOE_]   3000
//  seoff  short[M_+1]      1002
#define SMEM_BYTES 80032

// ---------------------------------------------------------------------------
// Accurate-but-fast transcendentals (validated in R3: rel_err 0.0).
// ---------------------------------------------------------------------------
__device__ __forceinline__ float tanh_clip_half(float x) {
    x = fminf(fmaxf(x, -9.9f), 9.9f);
    float ax = fabsf(x);
    float x2 = x * x;
    float num = x * fmaf(x2, fmaf(x2, 1.0f, 105.0f), 945.0f);
    float den = fmaf(x2, fmaf(x2, 15.0f, 420.0f), 945.0f);
    float tp  = __fdividef(num, den);
    float e   = __expf(2.0f * ax);
    float te  = copysignf(1.0f - __fdividef(2.0f, e + 1.0f), x);
    float t   = (ax < 1.0f) ? tp : te;
    return (t >= 0.f) ? fmaxf(t, 1e-7f) : fminf(t, -1e-7f);
}

__device__ __forceinline__ float atanh2_acc(float r) {
    r = fminf(fmaxf(r, -0.999999f), 0.999999f);
    float r2 = r * r;
    float poly = r * fmaf(r2, fmaf(r2, fmaf(r2, 0.28571428571f, 0.4f), 0.66666666667f), 2.0f);
    float q  = __fdividef(1.0f + r, 1.0f - r);
    float lg = __logf(q);
    return (fabsf(r) < 0.25f) ? poly : lg;
}

// ---------------------------------------------------------------------------
// Setup: single-block CSR build (count -> prefix -> place -> sort ascending,
// matching jax segment_prod accumulation order).
// ---------------------------------------------------------------------------
__global__ void setup_all_kernel(const int* __restrict__ cn) {
    __shared__ int cnt[M_];
    __shared__ int base[M_ + 1];
    const int t = threadIdx.x;  // 512
    for (int m = t; m < M_; m += 512) cnt[m] = 0;
    __syncthreads();
    for (int e = t; e < NINFOE_; e += 512) atomicAdd(&cnt[cn[e]], 1);
    __syncthreads();
    if (t == 0) {
        int run = 0;
        for (int m = 0; m < M_; m++) { base[m] = run; run += cnt[m]; }
        base[M_] = run;
    }
    __syncthreads();
    for (int m = t; m < M_; m += 512) cnt[m] = 0;
    __syncthreads();
    for (int e = t; e < NINFOE_; e += 512) {
        int c = cn[e];
        int slot = atomicAdd(&cnt[c], 1);
        g_elist[base[c] + slot] = (short)e;
    }
    __syncthreads();
    for (int m = t; m <= M_; m += 512) g_eoff[m] = (short)base[m];
    __syncthreads();
    for (int m = t; m < M_; m += 512) {
        int o0 = base[m], o1 = base[m + 1];
        for (int i = o0 + 1; i < o1; i++) {
            short v = g_elist[i];
            int j = i - 1;
            while (j >= o0 && g_elist[j] > v) { g_elist[j + 1] = g_elist[j]; j--; }
            g_elist[j + 1] = v;
        }
    }
}

// ---------------------------------------------------------------------------
// Mega kernel: one block per batch element.
//   phase 1: encode 4 UEs (parity via CSR) into shared bits
//   phase 2: 250 threads run one RE each: modulate, channel, Woodbury LMMSE,
//            separable max-log demap -> LLRs into shared
//   phase 3: decode 4 codewords as float4 lanes, all in shared
// ---------------------------------------------------------------------------
extern __shared__ unsigned char dynsmem[];

__global__ __launch_bounds__(256)
void mega_kernel(const int* __restrict__ bin,
                 const float4* __restrict__ hre4, const float4* __restrict__ him4,
                 const float4* __restrict__ nre4, const float4* __restrict__ nim4,
                 const float* __restrict__ ebno,
                 float* __restrict__ out_bf, float* __restrict__ out_bh)
{
    float4* sL = (float4*)dynsmem;                       // [N_]
    float4* sC = sL + N_;                                // [NINFOE_]
    float4* sT = sC + NINFOE_;                           // [NEDGE_]
    unsigned char* bits = (unsigned char*)(sT + NEDGE_); // [4*N_]
    short* selist = (short*)(bits + 4 * N_);             // [NINFOE_]
    short* seoff  = selist + NINFOE_;                    // [M_+1]

    const int b = blockIdx.x;
    const int t = threadIdx.x;

    // ---- load CSR + info bits, emit bf output ----
    for (int e = t; e < NINFOE_; e += 256) selist[e] = g_elist[e];
    for (int m = t; m <= M_; m += 256) seoff[m] = g_eoff[m];
    const int* bb = bin + (size_t)b * NUE_ * K_;
    float* of = out_bf + (size_t)b * NUE_ * K_;
    for (int i = t; i < NUE_ * K_; i += 256) {
        int ue = i / K_, n = i - ue * K_;
        int bit = bb[i];
        bits[ue * N_ + n] = (unsigned char)bit;
        of[i] = (float)bit;
    }
    for (int e = t; e < NINFOE_; e += 256) sC[e] = make_float4(0.f, 0.f, 0.f, 0.f);
    __syncthreads();

    // ---- parity ----
    for (int i = t; i < NUE_ * M_; i += 256) {
        int ue = i / M_, m = i - ue * M_;
        int o0 = seoff[m], o1 = seoff[m + 1];
        int par = 0;
        for (int q = o0; q < o1; q++) par ^= bits[ue * N_ + selist[q] / 3];
        bits[ue * N_ + K_ + m] = (unsigned char)par;
    }
    __syncthreads();

    // ---- LMMSE per RE ----
    if (t < NSYM_) {
        const float no  = 1.0f / (exp10f(ebno[0] * 0.1f) * 2.0f);
        const int r = b * NSYM_ + t;
        const float is2 = 0.70710678118654752440f;
        const float s10 = 0.31622776601683794f;

        float hr[4][4], hi[4][4];
#pragma unroll
        for (int i = 0; i < 4; i++) {
            float4 vr = hre4[r * 4 + i];
            float4 vi = him4[r * 4 + i];
            hr[i][0] = vr.x * is2; hr[i][1] = vr.y * is2; hr[i][2] = vr.z * is2; hr[i][3] = vr.w * is2;
            hi[i][0] = vi.x * is2; hi[i][1] = vi.y * is2; hi[i][2] = vi.z * is2; hi[i][3] = vi.w * is2;
        }

        // modulate from shared bits
        float xr[4], xi[4];
#pragma unroll
        for (int j = 0; j < 4; j++) {
            uchar4 cb = *(const uchar4*)&bits[j * N_ + 4 * t];
            xr[j] = (float)((1 - 2 * (int)cb.x) * (1 + 2 * (int)cb.z)) * s10;
            xi[j] = (float)((1 - 2 * (int)cb.y) * (1 + 2 * (int)cb.w)) * s10;
        }

        // y = H x + w
        const float ns = sqrtf(no * 0.5f);
        float4 wr4 = nre4[r], wi4 = nim4[r];
        float yr[4] = {wr4.x * ns, wr4.y * ns, wr4.z * ns, wr4.w * ns};
        float yi[4] = {wi4.x * ns, wi4.y * ns, wi4.z * ns, wi4.w * ns};
#pragma unroll
        for (int i = 0; i < 4; i++)
#pragma unroll
            for (int j = 0; j < 4; j++) {
                yr[i] += hr[i][j] * xr[j] - hi[i][j] * xi[j];
                yi[i] += hr[i][j] * xi[j] + hi[i][j] * xr[j];
            }

        // rhs = H^H y
        float rr[4], ri[4];
#pragma unroll
        for (int j = 0; j < 4; j++) {
            float ar = 0.f, ai = 0.f;
#pragma unroll
            for (int i = 0; i < 4; i++) {
                ar += hr[i][j] * yr[i] + hi[i][j] * yi[i];
                ai += hr[i][j] * yi[i] - hi[i][j] * yr[i];
            }
            rr[j] = ar; ri[j] = ai;
        }

        // B = H^H H + no*I (lower triangle, row j >= col k)
        float Br[4][4], Bi[4][4];
#pragma unroll
        for (int j = 0; j < 4; j++)
#pragma unroll
            for (int k = 0; k < 4; k++) {
                if (k > j) continue;
                float ar = (j == k) ? no : 0.f;
                float ai = 0.f;
#pragma unroll
                for (int i = 0; i < 4; i++) {
                    ar += hr[i][j] * hr[i][k] + hi[i][j] * hi[i][k];
                    ai += hr[i][j] * hi[i][k] - hi[i][j] * hr[i][k];
                }
                Br[j][k] = ar; Bi[j][k] = ai;
            }

        // Cholesky B = L L^H (in place), rk[k] = 1/L[k][k]
        float rk[4];
#pragma unroll
        for (int k = 0; k < 4; k++) {
            float v = Br[k][k];
#pragma unroll
            for (int j = 0; j < 4; j++)
                if (j < k) v -= Br[k][j] * Br[k][j] + Bi[k][j] * Bi[k][j];
            float inv = rsqrtf(v);
            rk[k] = inv;
#pragma unroll
            for (int i = 0; i < 4; i++) {
                if (i <= k) continue;
                float cr = Br[i][k], ci = Bi[i][k];
#pragma unroll
                for (int j = 0; j < 4; j++)
                    if (j < k) {
                        cr -= Br[i][j] * Br[k][j] + Bi[i][j] * Bi[k][j];
                        ci -= Bi[i][j] * Br[k][j] - Br[i][j] * Bi[k][j];
                    }
                Br[i][k] = cr * inv; Bi[i][k] = ci * inv;
            }
        }

        // solve L v = rhs, then L^H xraw = v
        float vr_[4], vi_[4];
#pragma unroll
        for (int i = 0; i < 4; i++) {
            float ar = rr[i], ai = ri[i];
#pragma unroll
            for (int j = 0; j < 4; j++)
                if (j < i) {
                    ar -= Br[i][j] * vr_[j] - Bi[i][j] * vi_[j];
                    ai -= Br[i][j] * vi_[j] + Bi[i][j] * vr_[j];
                }
            vr_[i] = ar * rk[i]; vi_[i] = ai * rk[i];
        }
        float xrw[4], xiw[4];
#pragma unroll
        for (int ii = 0; ii < 4; ii++) {
            int i = 3 - ii;
            float ar = vr_[i], ai = vi_[i];
#pragma unroll
            for (int j = 0; j < 4; j++)
                if (j > i) {
                    ar -= Br[j][i] * xrw[j] + Bi[j][i] * xiw[j];
                    ai -= Br[j][i] * xiw[j] - Bi[j][i] * xrw[j];
                }
            xrw[i] = ar * rk[i]; xiw[i] = ai * rk[i];
        }

        // diag(B^{-1})_j = || column j of L^{-1} ||^2
        float dj[4];
#pragma unroll
        for (int j = 0; j < 4; j++) {
            float wr[4], wi[4];
#pragma unroll
            for (int i = 0; i < 4; i++) { wr[i] = 0.f; wi[i] = 0.f; }
            wr[j] = rk[j];
            float acc = rk[j] * rk[j];
#pragma unroll
            for (int i = 0; i < 4; i++) {
                if (i <= j) continue;
                float sr = 0.f, si = 0.f;
#pragma unroll
                for (int q = 0; q < 4; q++)
                    if (q >= j && q < i) {
                        sr += Br[i][q] * wr[q] - Bi[i][q] * wi[q];
                        si += Br[i][q] * wi[q] + Bi[i][q] * wr[q];
                    }
                wr[i] = -sr * rk[i]; wi[i] = -si * rk[i];
                acc += wr[i] * wr[i] + wi[i] * wi[i];
            }
            dj[j] = acc;
        }

        // demap per UE (separable max-log) -> LLRs into shared
        float* sLf = (float*)sL;
#pragma unroll
        for (int c = 0; c < 4; c++) {
            float d = 1.0f - no * dj[c];
            float invd = 1.0f / d;
            float xhr = xrw[c] * invd, xhi = xiw[c] * invd;
            float noeff = fmaxf(invd - 1.0f, 1e-12f);
            float inoe = 1.0f / noeff;

            float a1  = xhr - s10,        a3  = xhr - 3.f * s10;
            float am1 = xhr + s10,        am3 = xhr + 3.f * s10;
            float f1 = -(a1 * a1), f3 = -(a3 * a3), fm1 = -(am1 * am1), fm3 = -(am3 * am3);
            float g1_  = xhi - s10,       g3_  = xhi - 3.f * s10;
            float gm1_ = xhi + s10,       gm3_ = xhi + 3.f * s10;
            float g1 = -(g1_ * g1_), g3 = -(g3_ * g3_), gm1 = -(gm1_ * gm1_), gm3 = -(gm3_ * gm3_);

            sLf[(4 * t + 0) * 4 + c] = (fmaxf(f1, f3) - fmaxf(fm1, fm3)) * inoe;   // b0
            sLf[(4 * t + 1) * 4 + c] = (fmaxf(g1, g3) - fmaxf(gm1, gm3)) * inoe;   // b1
            sLf[(4 * t + 2) * 4 + c] = (fmaxf(f1, fm1) - fmaxf(f3, fm3)) * inoe;   // b2
            sLf[(4 * t + 3) * 4 + c] = (fmaxf(g1, gm1) - fmaxf(g3, gm3)) * inoe;   // b3
        }
    }
    __syncthreads();

    // ---- decode: 4 codewords as float4 lanes ----
    // parity-edge tanh (loop-invariant: m_vc = Lch always)
    for (int m = t; m < M_; m += 256) {
        float4 l = sL[K_ + m];
        float4 tp;
        tp.x = tanh_clip_half(l.x * 0.5f);
        tp.y = tanh_clip_half(l.y * 0.5f);
        tp.z = tanh_clip_half(l.z * 0.5f);
        tp.w = tanh_clip_half(l.w * 0.5f);
        sT[NINFOE_ + m] = tp;
    }

    for (int it = 0; it < NITER_; it++) {
        // info variables: vtot + 3 v->c tanh
        for (int n = t; n < K_; n += 256) {
            float4 c0 = sC[3 * n], c1 = sC[3 * n + 1], c2 = sC[3 * n + 2];
            float4 l = sL[n];
            float vx = l.x + c0.x + c1.x + c2.x;
            float vy = l.y + c0.y + c1.y + c2.y;
            float vz = l.z + c0.z + c1.z + c2.z;
            float vw = l.w + c0.w + c1.w + c2.w;
            float4 o;
            o.x = tanh_clip_half((vx - c0.x) * 0.5f);
            o.y = tanh_clip_half((vy - c0.y) * 0.5f);
            o.z = tanh_clip_half((vz - c0.z) * 0.5f);
            o.w = tanh_clip_half((vw - c0.w) * 0.5f);
            sT[3 * n] = o;
            o.x = tanh_clip_half((vx - c1.x) * 0.5f);
            o.y = tanh_clip_half((vy - c1.y) * 0.5f);
            o.z = tanh_clip_half((vz - c1.z) * 0.5f);
            o.w = tanh_clip_half((vw - c1.w) * 0.5f);
            sT[3 * n + 1] = o;
            o.x = tanh_clip_half((vx - c2.x) * 0.5f);
            o.y = tanh_clip_half((vy - c2.y) * 0.5f);
            o.z = tanh_clip_half((vz - c2.z) * 0.5f);
            o.w = tanh_clip_half((vw - c2.w) * 0.5f);
            sT[3 * n + 2] = o;
        }
        __syncthreads();
        // checks: product (info edges ascending, then parity), then c2v
        for (int m = t; m < M_; m += 256) {
            int o0 = seoff[m], o1 = seoff[m + 1];
            float4 p = make_float4(1.f, 1.f, 1.f, 1.f);
            for (int q = o0; q < o1; q++) {
                float4 tt = sT[selist[q]];
                p.x *= tt.x; p.y *= tt.y; p.z *= tt.z; p.w *= tt.w;
            }
            float4 tp = sT[NINFOE_ + m];
            p.x *= tp.x; p.y *= tp.y; p.z *= tp.z; p.w *= tp.w;
            for (int q = o0; q < o1; q++) {
                int e = selist[q];
                float4 tt = sT[e];
                float4 c;
                c.x = atanh2_acc(__fdividef(p.x, tt.x));
                c.y = atanh2_acc(__fdividef(p.y, tt.y));
                c.z = atanh2_acc(__fdividef(p.z, tt.z));
                c.w = atanh2_acc(__fdividef(p.w, tt.w));
                sC[e] = c;
            }
        }
        __syncthreads();
    }

    // final hard decision
    float* oh = out_bh + (size_t)b * NUE_ * K_;
    for (int n = t; n < K_; n += 256) {
        float4 c0 = sC[3 * n], c1 = sC[3 * n + 1], c2 = sC[3 * n + 2];
        float4 l = sL[n];
        oh[0 * K_ + n] = (l.x + c0.x + c1.x + c2.x < 0.f) ? 1.0f : 0.0f;
        oh[1 * K_ + n] = (l.y + c0.y + c1.y + c2.y < 0.f) ? 1.0f : 0.0f;
        oh[2 * K_ + n] = (l.z + c0.z + c1.z + c2.z < 0.f) ? 1.0f : 0.0f;
        oh[3 * K_ + n] = (l.w + c0.w + c1.w + c2.w < 0.f) ? 1.0f : 0.0f;
    }
}

// ---------------------------------------------------------------------------
extern "C" void kernel_launch(void* const* d_in, const int* in_sizes, int n_in,
                              void* d_out, int out_size) {
    int shift = 10 - n_in;
    const float* ebno = (const float*)d_in[1 - shift];
    const int*   b    = (const int*)  d_in[2 - shift];
    const int*   cn   = (const int*)  d_in[4 - shift];
    const float* h_re = (const float*)d_in[6 - shift];
    const float* h_im = (const float*)d_in[7 - shift];
    const float* n_re = (const float*)d_in[8 - shift];
    const float* n_im = (const float*)d_in[9 - shift];

    float* out_bf = (float*)d_out;                       // (batch, NUE, K)
    float* out_bh = (float*)d_out + BATCH * NUE_ * K_;   // (batch, NUE, K)

    cudaFuncSetAttribute(mega_kernel, cudaFuncAttributeMaxDynamicSharedMemorySize, SMEM_BYTES);

    setup_all_kernel<<<1, 512>>>(cn);
    mega_kernel<<<BATCH, 256, SMEM_BYTES>>>(b,
                                            (const float4*)h_re, (const float4*)h_im,
                                            (const float4*)n_re, (const float4*)n_im,
                                            ebno, out_bf, out_bh);
}

// round 5
// speedup vs baseline: 1.1525x; 1.1525x over previous
#include <cuda_runtime.h>

// Problem constants (fixed by reference)
#define BATCH   1000
#define NUE_    4
#define K_      500
#define M_      500
#define N_      1000
#define NSYM_   250
#define NEDGE_  2000
#define NINFOE_ 1500
#define NITER_  5

// Static scratch
__device__ float g_llr[BATCH * NUE_ * N_];   // channel LLRs
__device__ short g_eoff[M_ + 1];
__device__ short g_elist[NINFOE_];

// ---------------------------------------------------------------------------
// Accurate-but-fast transcendentals (validated R3/R4: rel_err 0.0).
// ---------------------------------------------------------------------------
__device__ __forceinline__ float tanh_clip_half(float x) {
    x = fminf(fmaxf(x, -9.9f), 9.9f);
    float ax = fabsf(x);
    float x2 = x * x;
    float num = x * fmaf(x2, fmaf(x2, 1.0f, 105.0f), 945.0f);
    float den = fmaf(x2, fmaf(x2, 15.0f, 420.0f), 945.0f);
    float tp  = __fdividef(num, den);
    float e   = __expf(2.0f * ax);
    float te  = copysignf(1.0f - __fdividef(2.0f, e + 1.0f), x);
    float t   = (ax < 1.0f) ? tp : te;
    return (t >= 0.f) ? fmaxf(t, 1e-7f) : fminf(t, -1e-7f);
}

__device__ __forceinline__ float atanh2_acc(float r) {
    r = fminf(fmaxf(r, -0.999999f), 0.999999f);
    float r2 = r * r;
    float poly = r * fmaf(r2, fmaf(r2, fmaf(r2, 0.28571428571f, 0.4f), 0.66666666667f), 2.0f);
    float q  = __fdividef(1.0f + r, 1.0f - r);
    float lg = __logf(q);
    return (fabsf(r) < 0.25f) ? poly : lg;
}

// ---------------------------------------------------------------------------
// Setup: single-block CSR build (ascending edge order per check -> matches
// jax segment_prod accumulation order).
// ---------------------------------------------------------------------------
__global__ void setup_all_kernel(const int* __restrict__ cn) {
    __shared__ int cnt[M_];
    __shared__ int base[M_ + 1];
    const int t = threadIdx.x;  // 512
    for (int m = t; m < M_; m += 512) cnt[m] = 0;
    __syncthreads();
    for (int e = t; e < NINFOE_; e += 512) atomicAdd(&cnt[cn[e]], 1);
    __syncthreads();
    if (t == 0) {
        int run = 0;
        for (int m = 0; m < M_; m++) { base[m] = run; run += cnt[m]; }
        base[M_] = run;
    }
    __syncthreads();
    for (int m = t; m < M_; m += 512) cnt[m] = 0;
    __syncthreads();
    for (int e = t; e < NINFOE_; e += 512) {
        int c = cn[e];
        int slot = atomicAdd(&cnt[c], 1);
        g_elist[base[c] + slot] = (short)e;
    }
    __syncthreads();
    for (int m = t; m <= M_; m += 512) g_eoff[m] = (short)base[m];
    __syncthreads();
    for (int m = t; m < M_; m += 512) {
        int o0 = base[m], o1 = base[m + 1];
        for (int i = o0 + 1; i < o1; i++) {
            short v = g_elist[i];
            int j = i - 1;
            while (j >= o0 && g_elist[j] > v) { g_elist[j + 1] = g_elist[j]; j--; }
            g_elist[j + 1] = v;
        }
    }
}

// ---------------------------------------------------------------------------
// Fused encode + LMMSE: one block per batch element (light smem, ~8KB).
//   phase 1: stage info bits, emit bf output, compute parity via CSR
//   phase 2: threads 0..249 each run one RE: modulate, channel, Woodbury
//            LMMSE (B = H^H H + no*I), separable max-log demap -> g_llr
// ---------------------------------------------------------------------------
__global__ __launch_bounds__(256)
void enc_lmmse_kernel(const int* __restrict__ bin,
                      const float4* __restrict__ hre4, const float4* __restrict__ him4,
                      const float4* __restrict__ nre4, const float4* __restrict__ nim4,
                      const float* __restrict__ ebno,
                      float* __restrict__ out_bf)
{
    __shared__ unsigned char bits[NUE_ * N_];
    __shared__ short selist[NINFOE_];
    __shared__ short seoff[M_ + 1];

    const int b = blockIdx.x;
    const int t = threadIdx.x;

    for (int e = t; e < NINFOE_; e += 256) selist[e] = g_elist[e];
    for (int m = t; m <= M_; m += 256) seoff[m] = g_eoff[m];
    const int* bb = bin + (size_t)b * NUE_ * K_;
    float* of = out_bf + (size_t)b * NUE_ * K_;
    for (int i = t; i < NUE_ * K_; i += 256) {
        int ue = i / K_, n = i - ue * K_;
        int bit = bb[i];
        bits[ue * N_ + n] = (unsigned char)bit;
        of[i] = (float)bit;
    }
    __syncthreads();

    for (int i = t; i < NUE_ * M_; i += 256) {
        int ue = i / M_, m = i - ue * M_;
        int o0 = seoff[m], o1 = seoff[m + 1];
        int par = 0;
        for (int q = o0; q < o1; q++) par ^= bits[ue * N_ + selist[q] / 3];
        bits[ue * N_ + K_ + m] = (unsigned char)par;
    }
    __syncthreads();

    if (t >= NSYM_) return;

    const float no  = 1.0f / (exp10f(ebno[0] * 0.1f) * 2.0f);
    const int r = b * NSYM_ + t;
    const float is2 = 0.70710678118654752440f;
    const float s10 = 0.31622776601683794f;

    float hr[4][4], hi[4][4];
#pragma unroll
    for (int i = 0; i < 4; i++) {
        float4 vr = hre4[r * 4 + i];
        float4 vi = him4[r * 4 + i];
        hr[i][0] = vr.x * is2; hr[i][1] = vr.y * is2; hr[i][2] = vr.z * is2; hr[i][3] = vr.w * is2;
        hi[i][0] = vi.x * is2; hi[i][1] = vi.y * is2; hi[i][2] = vi.z * is2; hi[i][3] = vi.w * is2;
    }

    // modulate from shared bits
    float xr[4], xi[4];
#pragma unroll
    for (int j = 0; j < 4; j++) {
        uchar4 cb = *(const uchar4*)&bits[j * N_ + 4 * t];
        xr[j] = (float)((1 - 2 * (int)cb.x) * (1 + 2 * (int)cb.z)) * s10;
        xi[j] = (float)((1 - 2 * (int)cb.y) * (1 + 2 * (int)cb.w)) * s10;
    }

    // y = H x + w
    const float ns = sqrtf(no * 0.5f);
    float4 wr4 = nre4[r], wi4 = nim4[r];
    float yr[4] = {wr4.x * ns, wr4.y * ns, wr4.z * ns, wr4.w * ns};
    float yi[4] = {wi4.x * ns, wi4.y * ns, wi4.z * ns, wi4.w * ns};
#pragma unroll
    for (int i = 0; i < 4; i++)
#pragma unroll
        for (int j = 0; j < 4; j++) {
            yr[i] += hr[i][j] * xr[j] - hi[i][j] * xi[j];
            yi[i] += hr[i][j] * xi[j] + hi[i][j] * xr[j];
        }

    // rhs = H^H y
    float rr[4], ri[4];
#pragma unroll
    for (int j = 0; j < 4; j++) {
        float ar = 0.f, ai = 0.f;
#pragma unroll
        for (int i = 0; i < 4; i++) {
            ar += hr[i][j] * yr[i] + hi[i][j] * yi[i];
            ai += hr[i][j] * yi[i] - hi[i][j] * yr[i];
        }
        rr[j] = ar; ri[j] = ai;
    }

    // B = H^H H + no*I (lower triangle)
    float Br[4][4], Bi[4][4];
#pragma unroll
    for (int j = 0; j < 4; j++)
#pragma unroll
        for (int k = 0; k < 4; k++) {
            if (k > j) continue;
            float ar = (j == k) ? no : 0.f;
            float ai = 0.f;
#pragma unroll
            for (int i = 0; i < 4; i++) {
                ar += hr[i][j] * hr[i][k] + hi[i][j] * hi[i][k];
                ai += hr[i][j] * hi[i][k] - hi[i][j] * hr[i][k];
            }
            Br[j][k] = ar; Bi[j][k] = ai;
        }

    // Cholesky B = L L^H in place, rk[k] = 1/L[k][k]
    float rk[4];
#pragma unroll
    for (int k = 0; k < 4; k++) {
        float v = Br[k][k];
#pragma unroll
        for (int j = 0; j < 4; j++)
            if (j < k) v -= Br[k][j] * Br[k][j] + Bi[k][j] * Bi[k][j];
        float inv = rsqrtf(v);
        rk[k] = inv;
#pragma unroll
        for (int i = 0; i < 4; i++) {
            if (i <= k) continue;
            float cr = Br[i][k], ci = Bi[i][k];
#pragma unroll
            for (int j = 0; j < 4; j++)
                if (j < k) {
                    cr -= Br[i][j] * Br[k][j] + Bi[i][j] * Bi[k][j];
                    ci -= Bi[i][j] * Br[k][j] - Br[i][j] * Bi[k][j];
                }
            Br[i][k] = cr * inv; Bi[i][k] = ci * inv;
        }
    }

    // solve L v = rhs, then L^H xraw = v
    float vr_[4], vi_[4];
#pragma unroll
    for (int i = 0; i < 4; i++) {
        float ar = rr[i], ai = ri[i];
#pragma unroll
        for (int j = 0; j < 4; j++)
            if (j < i) {
                ar -= Br[i][j] * vr_[j] - Bi[i][j] * vi_[j];
                ai -= Br[i][j] * vi_[j] + Bi[i][j] * vr_[j];
            }
        vr_[i] = ar * rk[i]; vi_[i] = ai * rk[i];
    }
    float xrw[4], xiw[4];
#pragma unroll
    for (int ii = 0; ii < 4; ii++) {
        int i = 3 - ii;
        float ar = vr_[i], ai = vi_[i];
#pragma unroll
        for (int j = 0; j < 4; j++)
            if (j > i) {
                ar -= Br[j][i] * xrw[j] + Bi[j][i] * xiw[j];
                ai -= Br[j][i] * xiw[j] - Bi[j][i] * xrw[j];
            }
        xrw[i] = ar * rk[i]; xiw[i] = ai * rk[i];
    }

    // diag(B^{-1})_j = || column j of L^{-1} ||^2
    float dj[4];
#pragma unroll
    for (int j = 0; j < 4; j++) {
        float wr[4], wi[4];
#pragma unroll
        for (int i = 0; i < 4; i++) { wr[i] = 0.f; wi[i] = 0.f; }
        wr[j] = rk[j];
        float acc = rk[j] * rk[j];
#pragma unroll
        for (int i = 0; i < 4; i++) {
            if (i <= j) continue;
            float sr = 0.f, si = 0.f;
#pragma unroll
            for (int q = 0; q < 4; q++)
                if (q >= j && q < i) {
                    sr += Br[i][q] * wr[q] - Bi[i][q] * wi[q];
                    si += Br[i][q] * wi[q] + Bi[i][q] * wr[q];
                }
            wr[i] = -sr * rk[i]; wi[i] = -si * rk[i];
            acc += wr[i] * wr[i] + wi[i] * wi[i];
        }
        dj[j] = acc;
    }

    // separable max-log demap -> g_llr (coalesced float4)
#pragma unroll
    for (int c = 0; c < 4; c++) {
        float d = 1.0f - no * dj[c];
        float invd = 1.0f / d;
        float xhr = xrw[c] * invd, xhi = xiw[c] * invd;
        float noeff = fmaxf(invd - 1.0f, 1e-12f);
        float inoe = 1.0f / noeff;

        float a1  = xhr - s10,  a3  = xhr - 3.f * s10;
        float am1 = xhr + s10,  am3 = xhr + 3.f * s10;
        float f1 = -(a1 * a1), f3 = -(a3 * a3), fm1 = -(am1 * am1), fm3 = -(am3 * am3);
        float g1_ = xhi - s10,  g3_ = xhi - 3.f * s10;
        float gm1_ = xhi + s10, gm3_ = xhi + 3.f * s10;
        float g1 = -(g1_ * g1_), g3 = -(g3_ * g3_), gm1 = -(gm1_ * gm1_), gm3 = -(gm3_ * gm3_);

        float4 out = make_float4((fmaxf(f1, f3)  - fmaxf(fm1, fm3)) * inoe,
                                 (fmaxf(g1, g3)  - fmaxf(gm1, gm3)) * inoe,
                                 (fmaxf(f1, fm1) - fmaxf(f3, fm3))  * inoe,
                                 (fmaxf(g1, gm1) - fmaxf(g3, gm3))  * inoe);
        *(float4*)&g_llr[(size_t)(b * NUE_ + c) * N_ + 4 * t] = out;
    }
}

// ---------------------------------------------------------------------------
// Decoder: one block per batch element, 4 codewords as float4 lanes,
// 512 threads (one check / one variable per thread).
// Parity vars (deg-1): tanh loop-invariant; their c2v never consumed.
// ---------------------------------------------------------------------------
extern __shared__ unsigned char dynsmem[];
#define DEC_SMEM (16000 + 24000 + 32000 + 3000 + 1002)

__global__ __launch_bounds__(512)
void decode_kernel(float* __restrict__ out_bhat) {
    float4* sL = (float4*)dynsmem;            // [N_]
    float4* sC = sL + N_;                     // [NINFOE_]
    float4* sT = sC + NINFOE_;                // [NEDGE_]
    short* selist = (short*)(sT + NEDGE_);    // [NINFOE_]
    short* seoff  = selist + NINFOE_;         // [M_+1]

    const int b = blockIdx.x;
    const int t = threadIdx.x;
    const float* Lg = g_llr;

    // load LLRs: lane l = codeword (b*4+l); element n -> sL[n].{x,y,z,w}
    for (int n = t; n < N_; n += 512) {
        float4 v;
        v.x = Lg[(size_t)(b * NUE_ + 0) * N_ + n];
        v.y = Lg[(size_t)(b * NUE_ + 1) * N_ + n];
        v.z = Lg[(size_t)(b * NUE_ + 2) * N_ + n];
        v.w = Lg[(size_t)(b * NUE_ + 3) * N_ + n];
        sL[n] = v;
    }
    for (int e = t; e < NINFOE_; e += 512) { sC[e] = make_float4(0.f, 0.f, 0.f, 0.f); selist[e] = g_elist[e]; }
    for (int m = t; m <= M_; m += 512) seoff[m] = g_eoff[m];
    __syncthreads();

    // parity-edge tanh is loop-invariant (m_vc = Lch always)
    if (t < M_) {
        float4 l = sL[K_ + t];
        float4 tp;
        tp.x = tanh_clip_half(l.x * 0.5f);
        tp.y = tanh_clip_half(l.y * 0.5f);
        tp.z = tanh_clip_half(l.z * 0.5f);
        tp.w = tanh_clip_half(l.w * 0.5f);
        sT[NINFOE_ + t] = tp;
    }

    for (int it = 0; it < NITER_; it++) {
        // info variables: vtot + 3 v->c tanh (one variable per thread)
        if (t < K_) {
            const int n = t;
            float4 c0 = sC[3 * n], c1 = sC[3 * n + 1], c2 = sC[3 * n + 2];
            float4 l = sL[n];
            float vx = l.x + c0.x + c1.x + c2.x;
            float vy = l.y + c0.y + c1.y + c2.y;
            float vz = l.z + c0.z + c1.z + c2.z;
            float vw = l.w + c0.w + c1.w + c2.w;
            float4 o;
            o.x = tanh_clip_half((vx - c0.x) * 0.5f);
            o.y = tanh_clip_half((vy - c0.y) * 0.5f);
            o.z = tanh_clip_half((vz - c0.z) * 0.5f);
            o.w = tanh_clip_half((vw - c0.w) * 0.5f);
            sT[3 * n] = o;
            o.x = tanh_clip_half((vx - c1.x) * 0.5f);
            o.y = tanh_clip_half((vy - c1.y) * 0.5f);
            o.z = tanh_clip_half((vz - c1.z) * 0.5f);
            o.w = tanh_clip_half((vw - c1.w) * 0.5f);
            sT[3 * n + 1] = o;
            o.x = tanh_clip_half((vx - c2.x) * 0.5f);
            o.y = tanh_clip_half((vy - c2.y) * 0.5f);
            o.z = tanh_clip_half((vz - c2.z) * 0.5f);
            o.w = tanh_clip_half((vw - c2.w) * 0.5f);
            sT[3 * n + 2] = o;
        }
        __syncthreads();
        // checks: product (info edges ascending, then parity), then c2v
        if (t < M_) {
            const int m = t;
            int o0 = seoff[m], o1 = seoff[m + 1];
            float4 p = sT[NINFOE_ + m];
            for (int q = o0; q < o1; q++) {
                float4 tt = sT[selist[q]];
                p.x *= tt.x; p.y *= tt.y; p.z *= tt.z; p.w *= tt.w;
            }
            for (int q = o0; q < o1; q++) {
                int e = selist[q];
                float4 tt = sT[e];
                float4 c;
                c.x = atanh2_acc(__fdividef(p.x, tt.x));
                c.y = atanh2_acc(__fdividef(p.y, tt.y));
                c.z = atanh2_acc(__fdividef(p.z, tt.z));
                c.w = atanh2_acc(__fdividef(p.w, tt.w));
                sC[e] = c;
            }
        }
        __syncthreads();
    }

    // final hard decision
    float* oh = out_bhat + (size_t)b * NUE_ * K_;
    if (t < K_) {
        const int n = t;
        float4 c0 = sC[3 * n], c1 = sC[3 * n + 1], c2 = sC[3 * n + 2];
        float4 l = sL[n];
        oh[0 * K_ + n] = (l.x + c0.x + c1.x + c2.x < 0.f) ? 1.0f : 0.0f;
        oh[1 * K_ + n] = (l.y + c0.y + c1.y + c2.y < 0.f) ? 1.0f : 0.0f;
        oh[2 * K_ + n] = (l.z + c0.z + c1.z + c2.z < 0.f) ? 1.0f : 0.0f;
        oh[3 * K_ + n] = (l.w + c0.w + c1.w + c2.w < 0.f) ? 1.0f : 0.0f;
    }
}

// ---------------------------------------------------------------------------
extern "C" void kernel_launch(void* const* d_in, const int* in_sizes, int n_in,
                              void* d_out, int out_size) {
    int shift = 10 - n_in;
    const float* ebno = (const float*)d_in[1 - shift];
    const int*   b    = (const int*)  d_in[2 - shift];
    const int*   cn   = (const int*)  d_in[4 - shift];
    const float* h_re = (const float*)d_in[6 - shift];
    const float* h_im = (const float*)d_in[7 - shift];
    const float* n_re = (const float*)d_in[8 - shift];
    const float* n_im = (const float*)d_in[9 - shift];

    float* out_bf = (float*)d_out;                       // (batch, NUE, K)
    float* out_bh = (float*)d_out + BATCH * NUE_ * K_;   // (batch, NUE, K)

    cudaFuncSetAttribute(decode_kernel, cudaFuncAttributeMaxDynamicSharedMemorySize, DEC_SMEM);

    setup_all_kernel<<<1, 512>>>(cn);
    enc_lmmse_kernel<<<BATCH, 256>>>(b,
                                     (const float4*)h_re, (const float4*)h_im,
                                     (const float4*)n_re, (const float4*)n_im,
                                     ebno, out_bf);
    decode_kernel<<<BATCH, 512, DEC_SMEM>>>(out_bh);
}

// round 6
// speedup vs baseline: 1.2261x; 1.0639x over previous
#include <cuda_runtime.h>

// Problem constants (fixed by reference)
#define BATCH   1000
#define NUE_    4
#define K_      500
#define M_      500
#define N_      1000
#define NSYM_   250
#define NEDGE_  2000
#define NINFOE_ 1500
#define NITER_  5

// Static scratch
__device__ float g_llr[BATCH * NUE_ * N_];   // channel LLRs
__device__ short g_eoff[M_ + 1];
__device__ short g_elist[NINFOE_];

// ---------------------------------------------------------------------------
// Accurate-but-fast transcendentals (validated R3-R5: rel_err 0.0).
// ---------------------------------------------------------------------------
__device__ __forceinline__ float tanh_clip_half(float x) {
    x = fminf(fmaxf(x, -9.9f), 9.9f);
    float ax = fabsf(x);
    float x2 = x * x;
    float num = x * fmaf(x2, fmaf(x2, 1.0f, 105.0f), 945.0f);
    float den = fmaf(x2, fmaf(x2, 15.0f, 420.0f), 945.0f);
    float tp  = __fdividef(num, den);
    float e   = __expf(2.0f * ax);
    float te  = copysignf(1.0f - __fdividef(2.0f, e + 1.0f), x);
    float t   = (ax < 1.0f) ? tp : te;
    return (t >= 0.f) ? fmaxf(t, 1e-7f) : fminf(t, -1e-7f);
}

__device__ __forceinline__ float atanh2_acc(float r) {
    r = fminf(fmaxf(r, -0.999999f), 0.999999f);
    float r2 = r * r;
    float poly = r * fmaf(r2, fmaf(r2, fmaf(r2, 0.28571428571f, 0.4f), 0.66666666667f), 2.0f);
    float q  = __fdividef(1.0f + r, 1.0f - r);
    float lg = __logf(q);
    return (fabsf(r) < 0.25f) ? poly : lg;
}

// v->c message via tanh addition formula: tanh((vt-c)/2) = (T - r)/(1 - T r),
// where T = tanh(vt/2) and r = tanh(c/2) = rho (stored by the check phase).
__device__ __forceinline__ float vc_msg(float T, float r) {
    float t = __fdividef(T - r, fmaf(-T, r, 1.0f));
    t = fminf(fmaxf(t, -1.0f), 1.0f);
    return (t >= 0.f) ? fmaxf(t, 1e-7f) : fminf(t, -1e-7f);
}

// ---------------------------------------------------------------------------
// Setup: single-block CSR build. Parallel prefix (warp shuffle scan),
// shared-memory placement + per-check insertion sort (ascending edge order
// matches jax segment_prod accumulation order).
// ---------------------------------------------------------------------------
__global__ void setup_all_kernel(const int* __restrict__ cn) {
    __shared__ int   cnt[M_];
    __shared__ int   base[M_];
    __shared__ int   wsum[16];
    __shared__ short sel[NINFOE_];
    const int t = threadIdx.x;     // 512
    const int lane = t & 31, wid = t >> 5;

    if (t < M_) cnt[t] = 0;
    __syncthreads();
    for (int e = t; e < NINFOE_; e += 512) atomicAdd(&cnt[cn[e]], 1);
    __syncthreads();

    int v = (t < M_) ? cnt[t] : 0;
    int x = v;
#pragma unroll
    for (int d = 1; d < 32; d <<= 1) {
        int n = __shfl_up_sync(0xffffffffu, x, d);
        if (lane >= d) x += n;
    }
    if (lane == 31) wsum[wid] = x;
    __syncthreads();
    if (wid == 0) {
        int s = (lane < 16) ? wsum[lane] : 0;
#pragma unroll
        for (int d = 1; d < 16; d <<= 1) {
            int n = __shfl_up_sync(0xffffffffu, s, d);
            if (lane >= d) s += n;
        }
        if (lane < 16) wsum[lane] = s;
    }
    __syncthreads();
    int incl = x + ((wid > 0) ? wsum[wid - 1] : 0);
    if (t < M_) {
        base[t] = incl - v;
        g_eoff[t] = (short)(incl - v);
        cnt[t] = 0;
    }
    if (t == 0) g_eoff[M_] = (short)NINFOE_;
    __syncthreads();

    for (int e = t; e < NINFOE_; e += 512) {
        int c = cn[e];
        int slot = atomicAdd(&cnt[c], 1);
        sel[base[c] + slot] = (short)e;
    }
    __syncthreads();
    if (t < M_) {
        int o0 = base[t], o1 = base[t] + cnt[t];
        for (int i = o0 + 1; i < o1; i++) {
            short vv = sel[i];
            int j = i - 1;
            while (j >= o0 && sel[j] > vv) { sel[j + 1] = sel[j]; j--; }
            sel[j + 1] = vv;
        }
    }
    __syncthreads();
    for (int e = t; e < NINFOE_; e += 512) g_elist[e] = sel[e];
}

// ---------------------------------------------------------------------------
// Fused encode + LMMSE: one block per batch element (light smem).
// ---------------------------------------------------------------------------
__global__ __launch_bounds__(256)
void enc_lmmse_kernel(const int* __restrict__ bin,
                      const float4* __restrict__ hre4, const float4* __restrict__ him4,
                      const float4* __restrict__ nre4, const float4* __restrict__ nim4,
                      const float* __restrict__ ebno,
                      float* __restrict__ out_bf)
{
    __shared__ unsigned char bits[NUE_ * N_];
    __shared__ short selist[NINFOE_];
    __shared__ short seoff[M_ + 1];

    const int b = blockIdx.x;
    const int t = threadIdx.x;

    for (int e = t; e < NINFOE_; e += 256) selist[e] = g_elist[e];
    for (int m = t; m <= M_; m += 256) seoff[m] = g_eoff[m];
    const int* bb = bin + (size_t)b * NUE_ * K_;
    float* of = out_bf + (size_t)b * NUE_ * K_;
    for (int i = t; i < NUE_ * K_; i += 256) {
        int ue = i / K_, n = i - ue * K_;
        int bit = bb[i];
        bits[ue * N_ + n] = (unsigned char)bit;
        of[i] = (float)bit;
    }
    __syncthreads();

    for (int i = t; i < NUE_ * M_; i += 256) {
        int ue = i / M_, m = i - ue * M_;
        int o0 = seoff[m], o1 = seoff[m + 1];
        int par = 0;
        for (int q = o0; q < o1; q++) par ^= bits[ue * N_ + selist[q] / 3];
        bits[ue * N_ + K_ + m] = (unsigned char)par;
    }
    __syncthreads();

    if (t >= NSYM_) return;

    const float no  = 1.0f / (exp10f(ebno[0] * 0.1f) * 2.0f);
    const int r = b * NSYM_ + t;
    const float is2 = 0.70710678118654752440f;
    const float s10 = 0.31622776601683794f;

    float hr[4][4], hi[4][4];
#pragma unroll
    for (int i = 0; i < 4; i++) {
        float4 vr = hre4[r * 4 + i];
        float4 vi = him4[r * 4 + i];
        hr[i][0] = vr.x * is2; hr[i][1] = vr.y * is2; hr[i][2] = vr.z * is2; hr[i][3] = vr.w * is2;
        hi[i][0] = vi.x * is2; hi[i][1] = vi.y * is2; hi[i][2] = vi.z * is2; hi[i][3] = vi.w * is2;
    }

    float xr[4], xi[4];
#pragma unroll
    for (int j = 0; j < 4; j++) {
        uchar4 cb = *(const uchar4*)&bits[j * N_ + 4 * t];
        xr[j] = (float)((1 - 2 * (int)cb.x) * (1 + 2 * (int)cb.z)) * s10;
        xi[j] = (float)((1 - 2 * (int)cb.y) * (1 + 2 * (int)cb.w)) * s10;
    }

    const float ns = sqrtf(no * 0.5f);
    float4 wr4 = nre4[r], wi4 = nim4[r];
    float yr[4] = {wr4.x * ns, wr4.y * ns, wr4.z * ns, wr4.w * ns};
    float yi[4] = {wi4.x * ns, wi4.y * ns, wi4.z * ns, wi4.w * ns};
#pragma unroll
    for (int i = 0; i < 4; i++)
#pragma unroll
        for (int j = 0; j < 4; j++) {
            yr[i] += hr[i][j] * xr[j] - hi[i][j] * xi[j];
            yi[i] += hr[i][j] * xi[j] + hi[i][j] * xr[j];
        }

    float rr[4], ri[4];
#pragma unroll
    for (int j = 0; j < 4; j++) {
        float ar = 0.f, ai = 0.f;
#pragma unroll
        for (int i = 0; i < 4; i++) {
            ar += hr[i][j] * yr[i] + hi[i][j] * yi[i];
            ai += hr[i][j] * yi[i] - hi[i][j] * yr[i];
        }
        rr[j] = ar; ri[j] = ai;
    }

    float Br[4][4], Bi[4][4];
#pragma unroll
    for (int j = 0; j < 4; j++)
#pragma unroll
        for (int k = 0; k < 4; k++) {
            if (k > j) continue;
            float ar = (j == k) ? no : 0.f;
            float ai = 0.f;
#pragma unroll
            for (int i = 0; i < 4; i++) {
                ar += hr[i][j] * hr[i][k] + hi[i][j] * hi[i][k];
                ai += hr[i][j] * hi[i][k] - hi[i][j] * hr[i][k];
            }
            Br[j][k] = ar; Bi[j][k] = ai;
        }

    float rk[4];
#pragma unroll
    for (int k = 0; k < 4; k++) {
        float v = Br[k][k];
#pragma unroll
        for (int j = 0; j < 4; j++)
            if (j < k) v -= Br[k][j] * Br[k][j] + Bi[k][j] * Bi[k][j];
        float inv = rsqrtf(v);
        rk[k] = inv;
#pragma unroll
        for (int i = 0; i < 4; i++) {
            if (i <= k) continue;
            float cr = Br[i][k], ci = Bi[i][k];
#pragma unroll
            for (int j = 0; j < 4; j++)
                if (j < k) {
                    cr -= Br[i][j] * Br[k][j] + Bi[i][j] * Bi[k][j];
                    ci -= Bi[i][j] * Br[k][j] - Br[i][j] * Bi[k][j];
                }
            Br[i][k] = cr * inv; Bi[i][k] = ci * inv;
        }
    }

    float vr_[4], vi_[4];
#pragma unroll
    for (int i = 0; i < 4; i++) {
        float ar = rr[i], ai = ri[i];
#pragma unroll
        for (int j = 0; j < 4; j++)
            if (j < i) {
                ar -= Br[i][j] * vr_[j] - Bi[i][j] * vi_[j];
                ai -= Br[i][j] * vi_[j] + Bi[i][j] * vr_[j];
            }
        vr_[i] = ar * rk[i]; vi_[i] = ai * rk[i];
    }
    float xrw[4], xiw[4];
#pragma unroll
    for (int ii = 0; ii < 4; ii++) {
        int i = 3 - ii;
        float ar = vr_[i], ai = vi_[i];
#pragma unroll
        for (int j = 0; j < 4; j++)
            if (j > i) {
                ar -= Br[j][i] * xrw[j] + Bi[j][i] * xiw[j];
                ai -= Br[j][i] * xiw[j] - Bi[j][i] * xrw[j];
            }
        xrw[i] = ar * rk[i]; xiw[i] = ai * rk[i];
    }

    float dj[4];
#pragma unroll
    for (int j = 0; j < 4; j++) {
        float wr[4], wi[4];
#pragma unroll
        for (int i = 0; i < 4; i++) { wr[i] = 0.f; wi[i] = 0.f; }
        wr[j] = rk[j];
        float acc = rk[j] * rk[j];
#pragma unroll
        for (int i = 0; i < 4; i++) {
            if (i <= j) continue;
            float sr = 0.f, si = 0.f;
#pragma unroll
            for (int q = 0; q < 4; q++)
                if (q >= j && q < i) {
                    sr += Br[i][q] * wr[q] - Bi[i][q] * wi[q];
                    si += Br[i][q] * wi[q] + Bi[i][q] * wr[q];
                }
            wr[i] = -sr * rk[i]; wi[i] = -si * rk[i];
            acc += wr[i] * wr[i] + wi[i] * wi[i];
        }
        dj[j] = acc;
    }

#pragma unroll
    for (int c = 0; c < 4; c++) {
        float d = 1.0f - no * dj[c];
        float invd = 1.0f / d;
        float xhr = xrw[c] * invd, xhi = xiw[c] * invd;
        float noeff = fmaxf(invd - 1.0f, 1e-12f);
        float inoe = 1.0f / noeff;

        float a1  = xhr - s10,  a3  = xhr - 3.f * s10;
        float am1 = xhr + s10,  am3 = xhr + 3.f * s10;
        float f1 = -(a1 * a1), f3 = -(a3 * a3), fm1 = -(am1 * am1), fm3 = -(am3 * am3);
        float g1_ = xhi - s10,  g3_ = xhi - 3.f * s10;
        float gm1_ = xhi + s10, gm3_ = xhi + 3.f * s10;
        float g1 = -(g1_ * g1_), g3 = -(g3_ * g3_), gm1 = -(gm1_ * gm1_), gm3 = -(gm3_ * gm3_);

        float4 out = make_float4((fmaxf(f1, f3)  - fmaxf(fm1, fm3)) * inoe,
                                 (fmaxf(g1, g3)  - fmaxf(gm1, gm3)) * inoe,
                                 (fmaxf(f1, fm1) - fmaxf(f3, fm3))  * inoe,
                                 (fmaxf(g1, gm1) - fmaxf(g3, gm3))  * inoe);
        *(float4*)&g_llr[(size_t)(b * NUE_ + c) * N_ + 4 * t] = out;
    }
}

// ---------------------------------------------------------------------------
// Decoder: one block per batch element, 4 codewords as float4 lanes, 512 thr.
// sT[e] double-duty: after variable phase = tanh(m_vc); after check phase =
// rho_e = tanh(c2v/2). Variable phase uses the tanh addition formula.
// ---------------------------------------------------------------------------
extern __shared__ unsigned char dynsmem[];
#define DEC_SMEM (16000 + 24000 + 32000 + 3000 + 1002)

__global__ __launch_bounds__(512)
void decode_kernel(float* __restrict__ out_bhat) {
    float4* sL = (float4*)dynsmem;            // [N_]
    float4* sC = sL + N_;                     // [NINFOE_]
    float4* sT = sC + NINFOE_;                // [NEDGE_]
    short* selist = (short*)(sT + NEDGE_);    // [NINFOE_]
    short* seoff  = selist + NINFOE_;         // [M_+1]

    const int b = blockIdx.x;
    const int t = threadIdx.x;
    const float* Lg = g_llr;

    for (int n = t; n < N_; n += 512) {
        float4 v;
        v.x = Lg[(size_t)(b * NUE_ + 0) * N_ + n];
        v.y = Lg[(size_t)(b * NUE_ + 1) * N_ + n];
        v.z = Lg[(size_t)(b * NUE_ + 2) * N_ + n];
        v.w = Lg[(size_t)(b * NUE_ + 3) * N_ + n];
        sL[n] = v;
    }
    for (int e = t; e < NINFOE_; e += 512) {
        sC[e] = make_float4(0.f, 0.f, 0.f, 0.f);
        sT[e] = make_float4(0.f, 0.f, 0.f, 0.f);   // rho = 0 initially
        selist[e] = g_elist[e];
    }
    for (int m = t; m <= M_; m += 512) seoff[m] = g_eoff[m];
    __syncthreads();

    // parity-edge tanh is loop-invariant (m_vc = Lch always)
    if (t < M_) {
        float4 l = sL[K_ + t];
        float4 tp;
        tp.x = tanh_clip_half(l.x * 0.5f);
        tp.y = tanh_clip_half(l.y * 0.5f);
        tp.z = tanh_clip_half(l.z * 0.5f);
        tp.w = tanh_clip_half(l.w * 0.5f);
        sT[NINFOE_ + t] = tp;
    }

    for (int it = 0; it < NITER_; it++) {
        // variables: T = tanh(vtot/2), then 3 messages via addition formula
        if (t < K_) {
            const int n = t;
            float4 c0 = sC[3 * n], c1 = sC[3 * n + 1], c2 = sC[3 * n + 2];
            float4 r0 = sT[3 * n], r1 = sT[3 * n + 1], r2 = sT[3 * n + 2];
            float4 l = sL[n];
            float Tx = tanh_clip_half((l.x + c0.x + c1.x + c2.x) * 0.5f);
            float Ty = tanh_clip_half((l.y + c0.y + c1.y + c2.y) * 0.5f);
            float Tz = tanh_clip_half((l.z + c0.z + c1.z + c2.z) * 0.5f);
            float Tw = tanh_clip_half((l.w + c0.w + c1.w + c2.w) * 0.5f);
            sT[3 * n    ] = make_float4(vc_msg(Tx, r0.x), vc_msg(Ty, r0.y), vc_msg(Tz, r0.z), vc_msg(Tw, r0.w));
            sT[3 * n + 1] = make_float4(vc_msg(Tx, r1.x), vc_msg(Ty, r1.y), vc_msg(Tz, r1.z), vc_msg(Tw, r1.w));
            sT[3 * n + 2] = make_float4(vc_msg(Tx, r2.x), vc_msg(Ty, r2.y), vc_msg(Tz, r2.z), vc_msg(Tw, r2.w));
        }
        __syncthreads();
        // checks: product (info edges ascending, then parity), then c2v;
        // overwrite sT[e] with clipped rho for next variable phase.
        if (t < M_) {
            const int m = t;
            int o0 = seoff[m], o1 = seoff[m + 1];
            float4 p = sT[NINFOE_ + m];
            for (int q = o0; q < o1; q++) {
                float4 tt = sT[selist[q]];
                p.x *= tt.x; p.y *= tt.y; p.z *= tt.z; p.w *= tt.w;
            }
            for (int q = o0; q < o1; q++) {
                int e = selist[q];
                float4 tt = sT[e];
                float4 rho;
                rho.x = fminf(fmaxf(__fdividef(p.x, tt.x), -0.999999f), 0.999999f);
                rho.y = fminf(fmaxf(__fdividef(p.y, tt.y), -0.999999f), 0.999999f);
                rho.z = fminf(fmaxf(__fdividef(p.z, tt.z), -0.999999f), 0.999999f);
                rho.w = fminf(fmaxf(__fdividef(p.w, tt.w), -0.999999f), 0.999999f);
                sT[e] = rho;
                float4 c;
                c.x = atanh2_acc(rho.x);
                c.y = atanh2_acc(rho.y);
                c.z = atanh2_acc(rho.z);
                c.w = atanh2_acc(rho.w);
                sC[e] = c;
            }
        }
        __syncthreads();
    }

    float* oh = out_bhat + (size_t)b * NUE_ * K_;
    if (t < K_) {
        const int n = t;
        float4 c0 = sC[3 * n], c1 = sC[3 * n + 1], c2 = sC[3 * n + 2];
        float4 l = sL[n];
        oh[0 * K_ + n] = (l.x + c0.x + c1.x + c2.x < 0.f) ? 1.0f : 0.0f;
        oh[1 * K_ + n] = (l.y + c0.y + c1.y + c2.y < 0.f) ? 1.0f : 0.0f;
        oh[2 * K_ + n] = (l.z + c0.z + c1.z + c2.z < 0.f) ? 1.0f : 0.0f;
        oh[3 * K_ + n] = (l.w + c0.w + c1.w + c2.w < 0.f) ? 1.0f : 0.0f;
    }
}

// ---------------------------------------------------------------------------
extern "C" void kernel_launch(void* const* d_in, const int* in_sizes, int n_in,
                              void* d_out, int out_size) {
    int shift = 10 - n_in;
    const float* ebno = (const float*)d_in[1 - shift];
    const int*   b    = (const int*)  d_in[2 - shift];
    const int*   cn   = (const int*)  d_in[4 - shift];
    const float* h_re = (const float*)d_in[6 - shift];
    const float* h_im = (const float*)d_in[7 - shift];
    const float* n_re = (const float*)d_in[8 - shift];
    const float* n_im = (const float*)d_in[9 - shift];

    float* out_bf = (float*)d_out;                       // (batch, NUE, K)
    float* out_bh = (float*)d_out + BATCH * NUE_ * K_;   // (batch, NUE, K)

    cudaFuncSetAttribute(decode_kernel, cudaFuncAttributeMaxDynamicSharedMemorySize, DEC_SMEM);

    setup_all_kernel<<<1, 512>>>(cn);
    enc_lmmse_kernel<<<BATCH, 256>>>(b,
                                     (const float4*)h_re, (const float4*)h_im,
                                     (const float4*)n_re, (const float4*)n_im,
                                     ebno, out_bf);
    decode_kernel<<<BATCH, 512, DEC_SMEM>>>(out_bh);
}

// round 7
// speedup vs baseline: 1.5669x; 1.2779x over previous
#include <cuda_runtime.h>

// Problem constants (fixed by reference)
#define BATCH   1000
#define NUE_    4
#define K_      500
#define M_      500
#define N_      1000
#define NSYM_   250
#define NEDGE_  2000
#define NINFOE_ 1500
#define NITER_  5

// Static scratch
__device__ float g_llr[BATCH * NUE_ * N_];   // channel LLRs
__device__ short g_eoff[M_ + 1];
__device__ short g_elist[NINFOE_];

// ---------------------------------------------------------------------------
// Accurate-but-fast transcendentals (validated R3-R6: rel_err 0.0).
// ---------------------------------------------------------------------------
__device__ __forceinline__ float tanh_clip_half(float x) {
    x = fminf(fmaxf(x, -9.9f), 9.9f);
    float ax = fabsf(x);
    float x2 = x * x;
    float num = x * fmaf(x2, fmaf(x2, 1.0f, 105.0f), 945.0f);
    float den = fmaf(x2, fmaf(x2, 15.0f, 420.0f), 945.0f);
    float tp  = __fdividef(num, den);
    float e   = __expf(2.0f * ax);
    float te  = copysignf(1.0f - __fdividef(2.0f, e + 1.0f), x);
    float t   = (ax < 1.0f) ? tp : te;
    return (t >= 0.f) ? fmaxf(t, 1e-7f) : fminf(t, -1e-7f);
}

__device__ __forceinline__ float atanh2_acc(float r) {
    r = fminf(fmaxf(r, -0.999999f), 0.999999f);
    float r2 = r * r;
    float poly = r * fmaf(r2, fmaf(r2, fmaf(r2, 0.28571428571f, 0.4f), 0.66666666667f), 2.0f);
    float q  = __fdividef(1.0f + r, 1.0f - r);
    float lg = __logf(q);
    return (fabsf(r) < 0.25f) ? poly : lg;
}

// v->c message via tanh addition formula: tanh((vt-c)/2) = (T - r)/(1 - T r)
__device__ __forceinline__ float vc_msg(float T, float r) {
    float t = __fdividef(T - r, fmaf(-T, r, 1.0f));
    t = fminf(fmaxf(t, -1.0f), 1.0f);
    return (t >= 0.f) ? fmaxf(t, 1e-7f) : fminf(t, -1e-7f);
}

// ---------------------------------------------------------------------------
// Fused encode + LMMSE. Block 0 additionally builds the check-node CSR
// (needed only by the decode kernel launched afterwards) — hidden in the
// wave structure. Parity is computed via shared atomicXor over cn edges,
// so no block needs the CSR here.
// ---------------------------------------------------------------------------
__global__ __launch_bounds__(256)
void enc_lmmse_kernel(const int* __restrict__ bin,
                      const int* __restrict__ cn,
                      const float4* __restrict__ hre4, const float4* __restrict__ him4,
                      const float4* __restrict__ nre4, const float4* __restrict__ nim4,
                      const float* __restrict__ ebno,
                      float* __restrict__ out_bf)
{
    __shared__ char scratch[12032];
    unsigned char* bits = (unsigned char*)scratch;      // [NUE_*N_] = 4000
    int* sp = (int*)(scratch + 4000);                   // [NUE_*M_] = 8000

    const int b = blockIdx.x;
    const int t = threadIdx.x;
    const int lane = t & 31, wid = t >> 5;

    // ---- block 0 only: build global CSR (aliases scratch; done before bits) ----
    if (b == 0) {
        int*   cnt  = (int*)scratch;            // [M_]   2000
        int*   base = (int*)(scratch + 2000);   // [M_]   2000
        int*   wsum = (int*)(scratch + 4000);   // [8]      32
        short* sel  = (short*)(scratch + 4032); // [NINFOE_] 3000

        for (int m = t; m < M_; m += 256) cnt[m] = 0;
        __syncthreads();
        for (int e = t; e < NINFOE_; e += 256) atomicAdd(&cnt[cn[e]], 1);
        __syncthreads();
        int v0 = (2 * t     < M_) ? cnt[2 * t]     : 0;
        int v1 = (2 * t + 1 < M_) ? cnt[2 * t + 1] : 0;
        int s = v0 + v1, x = s;
#pragma unroll
        for (int d = 1; d < 32; d <<= 1) {
            int nn = __shfl_up_sync(0xffffffffu, x, d);
            if (lane >= d) x += nn;
        }
        if (lane == 31) wsum[wid] = x;
        __syncthreads();
        if (wid == 0) {
            int s2 = (lane < 8) ? wsum[lane] : 0;
#pragma unroll
            for (int d = 1; d < 8; d <<= 1) {
                int nn = __shfl_up_sync(0xffffffffu, s2, d);
                if (lane >= d) s2 += nn;
            }
            if (lane < 8) wsum[lane] = s2;
        }
        __syncthreads();
        int ex = x + ((wid > 0) ? wsum[wid - 1] : 0) - s;
        if (2 * t     < M_) { base[2 * t]     = ex;      g_eoff[2 * t]     = (short)ex; }
        if (2 * t + 1 < M_) { base[2 * t + 1] = ex + v0; g_eoff[2 * t + 1] = (short)(ex + v0); }
        if (t == 0) g_eoff[M_] = (short)NINFOE_;
        __syncthreads();
        for (int m = t; m < M_; m += 256) cnt[m] = 0;
        __syncthreads();
        for (int e = t; e < NINFOE_; e += 256) {
            int c = cn[e];
            int sl = atomicAdd(&cnt[c], 1);
            sel[base[c] + sl] = (short)e;
        }
        __syncthreads();
        for (int m = t; m < M_; m += 256) {
            int o0 = base[m], o1 = o0 + cnt[m];
            for (int i = o0 + 1; i < o1; i++) {
                short vv = sel[i];
                int j = i - 1;
                while (j >= o0 && sel[j] > vv) { sel[j + 1] = sel[j]; j--; }
                sel[j + 1] = vv;
            }
        }
        __syncthreads();
        for (int e = t; e < NINFOE_; e += 256) g_elist[e] = sel[e];
        __syncthreads();
    }

    // ---- stage info bits, emit bf output, zero parity accumulators ----
    const int* bb = bin + (size_t)b * NUE_ * K_;
    float* of = out_bf + (size_t)b * NUE_ * K_;
    for (int i = t; i < NUE_ * K_; i += 256) {
        int ue = i / K_, n = i - ue * K_;
        int bit = bb[i];
        bits[ue * N_ + n] = (unsigned char)bit;
        of[i] = (float)bit;
    }
    for (int i = t; i < NUE_ * M_; i += 256) sp[i] = 0;
    __syncthreads();

    // ---- parity via atomicXor over info edges (vn[e] = e/3 analytically) ----
    for (int e = t; e < NINFOE_; e += 256) {
        int c = cn[e], v = e / 3;
#pragma unroll
        for (int ue = 0; ue < 4; ue++)
            if (bits[ue * N_ + v]) atomicXor(&sp[ue * M_ + c], 1);
    }
    __syncthreads();
    for (int i = t; i < NUE_ * M_; i += 256) {
        int ue = i / M_, m = i - ue * M_;
        bits[ue * N_ + K_ + m] = (unsigned char)sp[i];
    }
    __syncthreads();

    if (t >= NSYM_) return;

    const float no  = 1.0f / (exp10f(ebno[0] * 0.1f) * 2.0f);
    const int r = b * NSYM_ + t;
    const float is2 = 0.70710678118654752440f;
    const float s10 = 0.31622776601683794f;

    float hr[4][4], hi[4][4];
#pragma unroll
    for (int i = 0; i < 4; i++) {
        float4 vr = hre4[r * 4 + i];
        float4 vi = him4[r * 4 + i];
        hr[i][0] = vr.x * is2; hr[i][1] = vr.y * is2; hr[i][2] = vr.z * is2; hr[i][3] = vr.w * is2;
        hi[i][0] = vi.x * is2; hi[i][1] = vi.y * is2; hi[i][2] = vi.z * is2; hi[i][3] = vi.w * is2;
    }

    float xr[4], xi[4];
#pragma unroll
    for (int j = 0; j < 4; j++) {
        uchar4 cb = *(const uchar4*)&bits[j * N_ + 4 * t];
        xr[j] = (float)((1 - 2 * (int)cb.x) * (1 + 2 * (int)cb.z)) * s10;
        xi[j] = (float)((1 - 2 * (int)cb.y) * (1 + 2 * (int)cb.w)) * s10;
    }

    const float ns = sqrtf(no * 0.5f);
    float4 wr4 = nre4[r], wi4 = nim4[r];
    float yr[4] = {wr4.x * ns, wr4.y * ns, wr4.z * ns, wr4.w * ns};
    float yi[4] = {wi4.x * ns, wi4.y * ns, wi4.z * ns, wi4.w * ns};
#pragma unroll
    for (int i = 0; i < 4; i++)
#pragma unroll
        for (int j = 0; j < 4; j++) {
            yr[i] += hr[i][j] * xr[j] - hi[i][j] * xi[j];
            yi[i] += hr[i][j] * xi[j] + hi[i][j] * xr[j];
        }

    float rr[4], ri[4];
#pragma unroll
    for (int j = 0; j < 4; j++) {
        float ar = 0.f, ai = 0.f;
#pragma unroll
        for (int i = 0; i < 4; i++) {
            ar += hr[i][j] * yr[i] + hi[i][j] * yi[i];
            ai += hr[i][j] * yi[i] - hi[i][j] * yr[i];
        }
        rr[j] = ar; ri[j] = ai;
    }

    float Br[4][4], Bi[4][4];
#pragma unroll
    for (int j = 0; j < 4; j++)
#pragma unroll
        for (int k = 0; k < 4; k++) {
            if (k > j) continue;
            float ar = (j == k) ? no : 0.f;
            float ai = 0.f;
#pragma unroll
            for (int i = 0; i < 4; i++) {
                ar += hr[i][j] * hr[i][k] + hi[i][j] * hi[i][k];
                ai += hr[i][j] * hi[i][k] - hi[i][j] * hr[i][k];
            }
            Br[j][k] = ar; Bi[j][k] = ai;
        }

    float rk[4];
#pragma unroll
    for (int k = 0; k < 4; k++) {
        float v = Br[k][k];
#pragma unroll
        for (int j = 0; j < 4; j++)
            if (j < k) v -= Br[k][j] * Br[k][j] + Bi[k][j] * Bi[k][j];
        float inv = rsqrtf(v);
        rk[k] = inv;
#pragma unroll
        for (int i = 0; i < 4; i++) {
            if (i <= k) continue;
            float cr = Br[i][k], ci = Bi[i][k];
#pragma unroll
            for (int j = 0; j < 4; j++)
                if (j < k) {
                    cr -= Br[i][j] * Br[k][j] + Bi[i][j] * Bi[k][j];
                    ci -= Bi[i][j] * Br[k][j] - Br[i][j] * Bi[k][j];
                }
            Br[i][k] = cr * inv; Bi[i][k] = ci * inv;
        }
    }

    float vr_[4], vi_[4];
#pragma unroll
    for (int i = 0; i < 4; i++) {
        float ar = rr[i], ai = ri[i];
#pragma unroll
        for (int j = 0; j < 4; j++)
            if (j < i) {
                ar -= Br[i][j] * vr_[j] - Bi[i][j] * vi_[j];
                ai -= Br[i][j] * vi_[j] + Bi[i][j] * vr_[j];
            }
        vr_[i] = ar * rk[i]; vi_[i] = ai * rk[i];
    }
    float xrw[4], xiw[4];
#pragma unroll
    for (int ii = 0; ii < 4; ii++) {
        int i = 3 - ii;
        float ar = vr_[i], ai = vi_[i];
#pragma unroll
        for (int j = 0; j < 4; j++)
            if (j > i) {
                ar -= Br[j][i] * xrw[j] + Bi[j][i] * xiw[j];
                ai -= Br[j][i] * xiw[j] - Bi[j][i] * xrw[j];
            }
        xrw[i] = ar * rk[i]; xiw[i] = ai * rk[i];
    }

    float dj[4];
#pragma unroll
    for (int j = 0; j < 4; j++) {
        float wr[4], wi[4];
#pragma unroll
        for (int i = 0; i < 4; i++) { wr[i] = 0.f; wi[i] = 0.f; }
        wr[j] = rk[j];
        float acc = rk[j] * rk[j];
#pragma unroll
        for (int i = 0; i < 4; i++) {
            if (i <= j) continue;
            float sr = 0.f, si = 0.f;
#pragma unroll
            for (int q = 0; q < 4; q++)
                if (q >= j && q < i) {
                    sr += Br[i][q] * wr[q] - Bi[i][q] * wi[q];
                    si += Br[i][q] * wi[q] + Bi[i][q] * wr[q];
                }
            wr[i] = -sr * rk[i]; wi[i] = -si * rk[i];
            acc += wr[i] * wr[i] + wi[i] * wi[i];
        }
        dj[j] = acc;
    }

#pragma unroll
    for (int c = 0; c < 4; c++) {
        float d = 1.0f - no * dj[c];
        float invd = 1.0f / d;
        float xhr = xrw[c] * invd, xhi = xiw[c] * invd;
        float noeff = fmaxf(invd - 1.0f, 1e-12f);
        float inoe = 1.0f / noeff;

        float a1  = xhr - s10,  a3  = xhr - 3.f * s10;
        float am1 = xhr + s10,  am3 = xhr + 3.f * s10;
        float f1 = -(a1 * a1), f3 = -(a3 * a3), fm1 = -(am1 * am1), fm3 = -(am3 * am3);
        float g1_ = xhi - s10,  g3_ = xhi - 3.f * s10;
        float gm1_ = xhi + s10, gm3_ = xhi + 3.f * s10;
        float g1 = -(g1_ * g1_), g3 = -(g3_ * g3_), gm1 = -(gm1_ * gm1_), gm3 = -(gm3_ * gm3_);

        float4 out = make_float4((fmaxf(f1, f3)  - fmaxf(fm1, fm3)) * inoe,
                                 (fmaxf(g1, g3)  - fmaxf(gm1, gm3)) * inoe,
                                 (fmaxf(f1, fm1) - fmaxf(f3, fm3))  * inoe,
                                 (fmaxf(g1, gm1) - fmaxf(g3, gm3))  * inoe);
        *(float4*)&g_llr[(size_t)(b * NUE_ + c) * N_ + 4 * t] = out;
    }
}

// ---------------------------------------------------------------------------
// Decoder: one block per batch element, 4 codewords as float4 lanes, 512 thr.
// No sC array: variable phase reconstructs c2v = atanh2(rho) from the rho
// stored in sT by the check phase (52KB smem -> 4 blocks/SM).
// ---------------------------------------------------------------------------
extern __shared__ unsigned char dynsmem[];
#define DEC_SMEM (16000 + 32000 + 3000 + 1002)

__global__ __launch_bounds__(512)
void decode_kernel(float* __restrict__ out_bhat) {
    float4* sL = (float4*)dynsmem;            // [N_]
    float4* sT = sL + N_;                     // [NEDGE_]
    short* selist = (short*)(sT + NEDGE_);    // [NINFOE_]
    short* seoff  = selist + NINFOE_;         // [M_+1]

    const int b = blockIdx.x;
    const int t = threadIdx.x;
    const float* Lg = g_llr;

    for (int n = t; n < N_; n += 512) {
        float4 v;
        v.x = Lg[(size_t)(b * NUE_ + 0) * N_ + n];
        v.y = Lg[(size_t)(b * NUE_ + 1) * N_ + n];
        v.z = Lg[(size_t)(b * NUE_ + 2) * N_ + n];
        v.w = Lg[(size_t)(b * NUE_ + 3) * N_ + n];
        sL[n] = v;
    }
    for (int e = t; e < NINFOE_; e += 512) {
        sT[e] = make_float4(0.f, 0.f, 0.f, 0.f);   // rho = 0 initially
        selist[e] = g_elist[e];
    }
    for (int m = t; m <= M_; m += 512) seoff[m] = g_eoff[m];
    __syncthreads();

    // parity-edge tanh is loop-invariant (m_vc = Lch always)
    if (t < M_) {
        float4 l = sL[K_ + t];
        float4 tp;
        tp.x = tanh_clip_half(l.x * 0.5f);
        tp.y = tanh_clip_half(l.y * 0.5f);
        tp.z = tanh_clip_half(l.z * 0.5f);
        tp.w = tanh_clip_half(l.w * 0.5f);
        sT[NINFOE_ + t] = tp;
    }

    for (int it = 0; it < NITER_; it++) {
        // variables: c_i = atanh2(rho_i); T = tanh(vtot/2); messages via
        // the addition formula. sT[e]: rho (in) -> tanh(m_vc) (out).
        if (t < K_) {
            const int n = t;
            float4 r0 = sT[3 * n], r1 = sT[3 * n + 1], r2 = sT[3 * n + 2];
            float4 l = sL[n];
            float vx = l.x + atanh2_acc(r0.x) + atanh2_acc(r1.x) + atanh2_acc(r2.x);
            float vy = l.y + atanh2_acc(r0.y) + atanh2_acc(r1.y) + atanh2_acc(r2.y);
            float vz = l.z + atanh2_acc(r0.z) + atanh2_acc(r1.z) + atanh2_acc(r2.z);
            float vw = l.w + atanh2_acc(r0.w) + atanh2_acc(r1.w) + atanh2_acc(r2.w);
            float Tx = tanh_clip_half(vx * 0.5f);
            float Ty = tanh_clip_half(vy * 0.5f);
            float Tz = tanh_clip_half(vz * 0.5f);
            float Tw = tanh_clip_half(vw * 0.5f);
            sT[3 * n    ] = make_float4(vc_msg(Tx, r0.x), vc_msg(Ty, r0.y), vc_msg(Tz, r0.z), vc_msg(Tw, r0.w));
            sT[3 * n + 1] = make_float4(vc_msg(Tx, r1.x), vc_msg(Ty, r1.y), vc_msg(Tz, r1.z), vc_msg(Tw, r1.w));
            sT[3 * n + 2] = make_float4(vc_msg(Tx, r2.x), vc_msg(Ty, r2.y), vc_msg(Tz, r2.z), vc_msg(Tw, r2.w));
        }
        __syncthreads();
        // checks: product (info edges ascending, then parity edge), then
        // overwrite sT[e] with clipped rho.
        if (t < M_) {
            const int m = t;
            int o0 = seoff[m], o1 = seoff[m + 1];
            float4 p = sT[NINFOE_ + m];
            for (int q = o0; q < o1; q++) {
                float4 tt = sT[selist[q]];
                p.x *= tt.x; p.y *= tt.y; p.z *= tt.z; p.w *= tt.w;
            }
            for (int q = o0; q < o1; q++) {
                int e = selist[q];
                float4 tt = sT[e];
                float4 rho;
                rho.x = fminf(fmaxf(__fdividef(p.x, tt.x), -0.999999f), 0.999999f);
                rho.y = fminf(fmaxf(__fdividef(p.y, tt.y), -0.999999f), 0.999999f);
                rho.z = fminf(fmaxf(__fdividef(p.z, tt.z), -0.999999f), 0.999999f);
                rho.w = fminf(fmaxf(__fdividef(p.w, tt.w), -0.999999f), 0.999999f);
                sT[e] = rho;
            }
        }
        __syncthreads();
    }

    // final hard decision: vtot from final rho
    float* oh = out_bhat + (size_t)b * NUE_ * K_;
    if (t < K_) {
        const int n = t;
        float4 r0 = sT[3 * n], r1 = sT[3 * n + 1], r2 = sT[3 * n + 2];
        float4 l = sL[n];
        float vx = l.x + atanh2_acc(r0.x) + atanh2_acc(r1.x) + atanh2_acc(r2.x);
        float vy = l.y + atanh2_acc(r0.y) + atanh2_acc(r1.y) + atanh2_acc(r2.y);
        float vz = l.z + atanh2_acc(r0.z) + atanh2_acc(r1.z) + atanh2_acc(r2.z);
        float vw = l.w + atanh2_acc(r0.w) + atanh2_acc(r1.w) + atanh2_acc(r2.w);
        oh[0 * K_ + n] = (vx < 0.f) ? 1.0f : 0.0f;
        oh[1 * K_ + n] = (vy < 0.f) ? 1.0f : 0.0f;
        oh[2 * K_ + n] = (vz < 0.f) ? 1.0f : 0.0f;
        oh[3 * K_ + n] = (vw < 0.f) ? 1.0f : 0.0f;
    }
}

// ---------------------------------------------------------------------------
extern "C" void kernel_launch(void* const* d_in, const int* in_sizes, int n_in,
                              void* d_out, int out_size) {
    int shift = 10 - n_in;
    const float* ebno = (const float*)d_in[1 - shift];
    const int*   b    = (const int*)  d_in[2 - shift];
    const int*   cn   = (const int*)  d_in[4 - shift];
    const float* h_re = (const float*)d_in[6 - shift];
    const float* h_im = (const float*)d_in[7 - shift];
    const float* n_re = (const float*)d_in[8 - shift];
    const float* n_im = (const float*)d_in[9 - shift];

    float* out_bf = (float*)d_out;                       // (batch, NUE, K)
    float* out_bh = (float*)d_out + BATCH * NUE_ * K_;   // (batch, NUE, K)

    cudaFuncSetAttribute(decode_kernel, cudaFuncAttributeMaxDynamicSharedMemorySize, DEC_SMEM);

    enc_lmmse_kernel<<<BATCH, 256>>>(b, cn,
                                     (const float4*)h_re, (const float4*)h_im,
                                     (const float4*)n_re, (const float4*)n_im,
                                     ebno, out_bf);
    decode_kernel<<<BATCH, 512, DEC_SMEM>>>(out_bh);
}

// round 8
// speedup vs baseline: 1.8847x; 1.2028x over previous
#include <cuda_runtime.h>

// Problem constants (fixed by reference)
#define BATCH   1000
#define NUE_    4
#define K_      500
#define M_      500
#define N_      1000
#define NSYM_   250
#define NEDGE_  2000
#define NINFOE_ 1500
#define NITER_  5

// Static scratch
__device__ float g_llr[BATCH * NUE_ * N_];   // channel LLRs
__device__ short g_eoff[M_ + 1];
__device__ short g_elist[NINFOE_];

// ---------------------------------------------------------------------------
// Transcendentals (hybrid tanh validated R3-R7: rel_err 0.0).
// ---------------------------------------------------------------------------
__device__ __forceinline__ float tanh_clip_half(float x) {
    x = fminf(fmaxf(x, -9.9f), 9.9f);
    float ax = fabsf(x);
    float x2 = x * x;
    float num = x * fmaf(x2, fmaf(x2, 1.0f, 105.0f), 945.0f);
    float den = fmaf(x2, fmaf(x2, 15.0f, 420.0f), 945.0f);
    float tp  = __fdividef(num, den);
    float e   = __expf(2.0f * ax);
    float te  = copysignf(1.0f - __fdividef(2.0f, e + 1.0f), x);
    float t   = (ax < 1.0f) ? tp : te;
    return (t >= 0.f) ? fmaxf(t, 1e-7f) : fminf(t, -1e-7f);
}

// vtot = L + 2*atanh(r0) + 2*atanh(r1) + 2*atanh(r2)
//      = L + log( (1+r0)(1+r1)(1+r2) / ((1-r0)(1-r1)(1-r2)) )
// (rhos pre-clipped to +-0.999999; den >= 1e-18, safe)
__device__ __forceinline__ float vtot_logprod(float L, float r0, float r1, float r2) {
    float num = (1.0f + r0) * (1.0f + r1) * (1.0f + r2);
    float den = (1.0f - r0) * (1.0f - r1) * (1.0f - r2);
    return L + __logf(__fdividef(num, den));
}

// v->c message via tanh addition formula: tanh((vt-c)/2) = (T - r)/(1 - T r)
__device__ __forceinline__ float vc_msg(float T, float r) {
    float t = __fdividef(T - r, fmaf(-T, r, 1.0f));
    return (t >= 0.f) ? fmaxf(t, 1e-7f) : fminf(t, -1e-7f);
}

// ---------------------------------------------------------------------------
// Fused encode + LMMSE. Block 0 additionally builds the check-node CSR
// (consumed only by the decode kernel) — hidden inside the wave structure.
// Parity via shared atomicXor over the raw cn edge list.
// ---------------------------------------------------------------------------
__global__ __launch_bounds__(256)
void enc_lmmse_kernel(const int* __restrict__ bin,
                      const int* __restrict__ cn,
                      const float4* __restrict__ hre4, const float4* __restrict__ him4,
                      const float4* __restrict__ nre4, const float4* __restrict__ nim4,
                      const float* __restrict__ ebno,
                      float* __restrict__ out_bf)
{
    __shared__ char scratch[12032];
    unsigned char* bits = (unsigned char*)scratch;      // [NUE_*N_] = 4000
    int* sp = (int*)(scratch + 4000);                   // [NUE_*M_] = 8000

    const int b = blockIdx.x;
    const int t = threadIdx.x;
    const int lane = t & 31, wid = t >> 5;

    // ---- block 0 only: build global CSR (aliases scratch; before bits) ----
    if (b == 0) {
        int*   cnt  = (int*)scratch;            // [M_]   2000
        int*   base = (int*)(scratch + 2000);   // [M_]   2000
        int*   wsum = (int*)(scratch + 4000);   // [8]      32
        short* sel  = (short*)(scratch + 4032); // [NINFOE_] 3000

        for (int m = t; m < M_; m += 256) cnt[m] = 0;
        __syncthreads();
        for (int e = t; e < NINFOE_; e += 256) atomicAdd(&cnt[cn[e]], 1);
        __syncthreads();
        int v0 = (2 * t     < M_) ? cnt[2 * t]     : 0;
        int v1 = (2 * t + 1 < M_) ? cnt[2 * t + 1] : 0;
        int s = v0 + v1, x = s;
#pragma unroll
        for (int d = 1; d < 32; d <<= 1) {
            int nn = __shfl_up_sync(0xffffffffu, x, d);
            if (lane >= d) x += nn;
        }
        if (lane == 31) wsum[wid] = x;
        __syncthreads();
        if (wid == 0) {
            int s2 = (lane < 8) ? wsum[lane] : 0;
#pragma unroll
            for (int d = 1; d < 8; d <<= 1) {
                int nn = __shfl_up_sync(0xffffffffu, s2, d);
                if (lane >= d) s2 += nn;
            }
            if (lane < 8) wsum[lane] = s2;
        }
        __syncthreads();
        int ex = x + ((wid > 0) ? wsum[wid - 1] : 0) - s;
        if (2 * t     < M_) { base[2 * t]     = ex;      g_eoff[2 * t]     = (short)ex; }
        if (2 * t + 1 < M_) { base[2 * t + 1] = ex + v0; g_eoff[2 * t + 1] = (short)(ex + v0); }
        if (t == 0) g_eoff[M_] = (short)NINFOE_;
        __syncthreads();
        for (int m = t; m < M_; m += 256) cnt[m] = 0;
        __syncthreads();
        for (int e = t; e < NINFOE_; e += 256) {
            int c = cn[e];
            int sl = atomicAdd(&cnt[c], 1);
            sel[base[c] + sl] = (short)e;
        }
        __syncthreads();
        for (int m = t; m < M_; m += 256) {
            int o0 = base[m], o1 = o0 + cnt[m];
            for (int i = o0 + 1; i < o1; i++) {
                short vv = sel[i];
                int j = i - 1;
                while (j >= o0 && sel[j] > vv) { sel[j + 1] = sel[j]; j--; }
                sel[j + 1] = vv;
            }
        }
        __syncthreads();
        for (int e = t; e < NINFOE_; e += 256) g_elist[e] = sel[e];
        __syncthreads();
    }

    // ---- stage info bits, emit bf output, zero parity accumulators ----
    const int* bb = bin + (size_t)b * NUE_ * K_;
    float* of = out_bf + (size_t)b * NUE_ * K_;
    for (int i = t; i < NUE_ * K_; i += 256) {
        int ue = i / K_, n = i - ue * K_;
        int bit = bb[i];
        bits[ue * N_ + n] = (unsigned char)bit;
        of[i] = (float)bit;
    }
    for (int i = t; i < NUE_ * M_; i += 256) sp[i] = 0;
    __syncthreads();

    // ---- parity via atomicXor over info edges (vn[e] = e/3 analytically) ----
    for (int e = t; e < NINFOE_; e += 256) {
        int c = cn[e], v = e / 3;
#pragma unroll
        for (int ue = 0; ue < 4; ue++)
            if (bits[ue * N_ + v]) atomicXor(&sp[ue * M_ + c], 1);
    }
    __syncthreads();
    for (int i = t; i < NUE_ * M_; i += 256) {
        int ue = i / M_, m = i - ue * M_;
        bits[ue * N_ + K_ + m] = (unsigned char)sp[i];
    }
    __syncthreads();

    if (t >= NSYM_) return;

    const float no  = 1.0f / (exp10f(ebno[0] * 0.1f) * 2.0f);
    const int r = b * NSYM_ + t;
    const float is2 = 0.70710678118654752440f;
    const float s10 = 0.31622776601683794f;

    float hr[4][4], hi[4][4];
#pragma unroll
    for (int i = 0; i < 4; i++) {
        float4 vr = hre4[r * 4 + i];
        float4 vi = him4[r * 4 + i];
        hr[i][0] = vr.x * is2; hr[i][1] = vr.y * is2; hr[i][2] = vr.z * is2; hr[i][3] = vr.w * is2;
        hi[i][0] = vi.x * is2; hi[i][1] = vi.y * is2; hi[i][2] = vi.z * is2; hi[i][3] = vi.w * is2;
    }

    float xr[4], xi[4];
#pragma unroll
    for (int j = 0; j < 4; j++) {
        uchar4 cb = *(const uchar4*)&bits[j * N_ + 4 * t];
        xr[j] = (float)((1 - 2 * (int)cb.x) * (1 + 2 * (int)cb.z)) * s10;
        xi[j] = (float)((1 - 2 * (int)cb.y) * (1 + 2 * (int)cb.w)) * s10;
    }

    const float ns = sqrtf(no * 0.5f);
    float4 wr4 = nre4[r], wi4 = nim4[r];
    float yr[4] = {wr4.x * ns, wr4.y * ns, wr4.z * ns, wr4.w * ns};
    float yi[4] = {wi4.x * ns, wi4.y * ns, wi4.z * ns, wi4.w * ns};
#pragma unroll
    for (int i = 0; i < 4; i++)
#pragma unroll
        for (int j = 0; j < 4; j++) {
            yr[i] += hr[i][j] * xr[j] - hi[i][j] * xi[j];
            yi[i] += hr[i][j] * xi[j] + hi[i][j] * xr[j];
        }

    float rr[4], ri[4];
#pragma unroll
    for (int j = 0; j < 4; j++) {
        float ar = 0.f, ai = 0.f;
#pragma unroll
        for (int i = 0; i < 4; i++) {
            ar += hr[i][j] * yr[i] + hi[i][j] * yi[i];
            ai += hr[i][j] * yi[i] - hi[i][j] * yr[i];
        }
        rr[j] = ar; ri[j] = ai;
    }

    float Br[4][4], Bi[4][4];
#pragma unroll
    for (int j = 0; j < 4; j++)
#pragma unroll
        for (int k = 0; k < 4; k++) {
            if (k > j) continue;
            float ar = (j == k) ? no : 0.f;
            float ai = 0.f;
#pragma unroll
            for (int i = 0; i < 4; i++) {
                ar += hr[i][j] * hr[i][k] + hi[i][j] * hi[i][k];
                ai += hr[i][j] * hi[i][k] - hi[i][j] * hr[i][k];
            }
            Br[j][k] = ar; Bi[j][k] = ai;
        }

    float rk[4];
#pragma unroll
    for (int k = 0; k < 4; k++) {
        float v = Br[k][k];
#pragma unroll
        for (int j = 0; j < 4; j++)
            if (j < k) v -= Br[k][j] * Br[k][j] + Bi[k][j] * Bi[k][j];
        float inv = rsqrtf(v);
        rk[k] = inv;
#pragma unroll
        for (int i = 0; i < 4; i++) {
            if (i <= k) continue;
            float cr = Br[i][k], ci = Bi[i][k];
#pragma unroll
            for (int j = 0; j < 4; j++)
                if (j < k) {
                    cr -= Br[i][j] * Br[k][j] + Bi[i][j] * Bi[k][j];
                    ci -= Bi[i][j] * Br[k][j] - Br[i][j] * Bi[k][j];
                }
            Br[i][k] = cr * inv; Bi[i][k] = ci * inv;
        }
    }

    float vr_[4], vi_[4];
#pragma unroll
    for (int i = 0; i < 4; i++) {
        float ar = rr[i], ai = ri[i];
#pragma unroll
        for (int j = 0; j < 4; j++)
            if (j < i) {
                ar -= Br[i][j] * vr_[j] - Bi[i][j] * vi_[j];
                ai -= Br[i][j] * vi_[j] + Bi[i][j] * vr_[j];
            }
        vr_[i] = ar * rk[i]; vi_[i] = ai * rk[i];
    }
    float xrw[4], xiw[4];
#pragma unroll
    for (int ii = 0; ii < 4; ii++) {
        int i = 3 - ii;
        float ar = vr_[i], ai = vi_[i];
#pragma unroll
        for (int j = 0; j < 4; j++)
            if (j > i) {
                ar -= Br[j][i] * xrw[j] + Bi[j][i] * xiw[j];
                ai -= Br[j][i] * xiw[j] - Bi[j][i] * xrw[j];
            }
        xrw[i] = ar * rk[i]; xiw[i] = ai * rk[i];
    }

    float dj[4];
#pragma unroll
    for (int j = 0; j < 4; j++) {
        float wr[4], wi[4];
#pragma unroll
        for (int i = 0; i < 4; i++) { wr[i] = 0.f; wi[i] = 0.f; }
        wr[j] = rk[j];
        float acc = rk[j] * rk[j];
#pragma unroll
        for (int i = 0; i < 4; i++) {
            if (i <= j) continue;
            float sr = 0.f, si = 0.f;
#pragma unroll
            for (int q = 0; q < 4; q++)
                if (q >= j && q < i) {
                    sr += Br[i][q] * wr[q] - Bi[i][q] * wi[q];
                    si += Br[i][q] * wi[q] + Bi[i][q] * wr[q];
                }
            wr[i] = -sr * rk[i]; wi[i] = -si * rk[i];
            acc += wr[i] * wr[i] + wi[i] * wi[i];
        }
        dj[j] = acc;
    }

#pragma unroll
    for (int c = 0; c < 4; c++) {
        float d = 1.0f - no * dj[c];
        float invd = 1.0f / d;
        float xhr = xrw[c] * invd, xhi = xiw[c] * invd;
        float noeff = fmaxf(invd - 1.0f, 1e-12f);
        float inoe = 1.0f / noeff;

        float a1  = xhr - s10,  a3  = xhr - 3.f * s10;
        float am1 = xhr + s10,  am3 = xhr + 3.f * s10;
        float f1 = -(a1 * a1), f3 = -(a3 * a3), fm1 = -(am1 * am1), fm3 = -(am3 * am3);
        float g1_ = xhi - s10,  g3_ = xhi - 3.f * s10;
        float gm1_ = xhi + s10, gm3_ = xhi + 3.f * s10;
        float g1 = -(g1_ * g1_), g3 = -(g3_ * g3_), gm1 = -(gm1_ * gm1_), gm3 = -(gm3_ * gm3_);

        float4 out = make_float4((fmaxf(f1, f3)  - fmaxf(fm1, fm3)) * inoe,
                                 (fmaxf(g1, g3)  - fmaxf(gm1, gm3)) * inoe,
                                 (fmaxf(f1, fm1) - fmaxf(f3, fm3))  * inoe,
                                 (fmaxf(g1, gm1) - fmaxf(g3, gm3))  * inoe);
        *(float4*)&g_llr[(size_t)(b * NUE_ + c) * N_ + 4 * t] = out;
    }
}

// ---------------------------------------------------------------------------
// Decoder: one block per batch element, 4 codewords as float4 lanes, 512 thr.
// State: sT[e] = tanh(m_vc/2) after variable phase, rho after check phase.
// Variable phase: vtot via ONE log of a product (== 3 atanh sums, exact
// linear domain); messages via tanh addition formula. Iter-1 variable
// phase special-cased (c2v = 0 -> all messages = tanh(L/2)).
// ---------------------------------------------------------------------------
extern __shared__ unsigned char dynsmem[];
#define DEC_SMEM (16000 + 32000 + 3000 + 1002)

__global__ __launch_bounds__(512)
void decode_kernel(float* __restrict__ out_bhat) {
    float4* sL = (float4*)dynsmem;            // [N_]
    float4* sT = sL + N_;                     // [NEDGE_]
    short* selist = (short*)(sT + NEDGE_);    // [NINFOE_]
    short* seoff  = selist + NINFOE_;         // [M_+1]

    const int b = blockIdx.x;
    const int t = threadIdx.x;
    const float* Lg = g_llr;

    for (int n = t; n < N_; n += 512) {
        float4 v;
        v.x = Lg[(size_t)(b * NUE_ + 0) * N_ + n];
        v.y = Lg[(size_t)(b * NUE_ + 1) * N_ + n];
        v.z = Lg[(size_t)(b * NUE_ + 2) * N_ + n];
        v.w = Lg[(size_t)(b * NUE_ + 3) * N_ + n];
        sL[n] = v;
    }
    for (int e = t; e < NINFOE_; e += 512) selist[e] = g_elist[e];
    for (int m = t; m <= M_; m += 512) seoff[m] = g_eoff[m];
    __syncthreads();

    // iter-1 variable phase: c2v = 0 -> all three messages = tanh(L/2)
    if (t < K_) {
        float4 l = sL[t];
        float4 T0;
        T0.x = tanh_clip_half(l.x * 0.5f);
        T0.y = tanh_clip_half(l.y * 0.5f);
        T0.z = tanh_clip_half(l.z * 0.5f);
        T0.w = tanh_clip_half(l.w * 0.5f);
        sT[3 * t] = T0; sT[3 * t + 1] = T0; sT[3 * t + 2] = T0;
    }
    // parity-edge tanh is loop-invariant (m_vc = Lch always)
    if (t < M_) {
        float4 l = sL[K_ + t];
        float4 tp;
        tp.x = tanh_clip_half(l.x * 0.5f);
        tp.y = tanh_clip_half(l.y * 0.5f);
        tp.z = tanh_clip_half(l.z * 0.5f);
        tp.w = tanh_clip_half(l.w * 0.5f);
        sT[NINFOE_ + t] = tp;
    }
    // hoist check CSR bounds into registers
    int co0 = 0, co1 = 0;
    if (t < M_) { co0 = seoff[t]; co1 = seoff[t + 1]; }
    __syncthreads();

    for (int it = 0; it < NITER_; it++) {
        // checks: product (info edges ascending, then parity edge), then
        // overwrite sT[e] with clipped rho.
        if (t < M_) {
            float4 p = sT[NINFOE_ + t];
            for (int q = co0; q < co1; q++) {
                float4 tt = sT[selist[q]];
                p.x *= tt.x; p.y *= tt.y; p.z *= tt.z; p.w *= tt.w;
            }
            for (int q = co0; q < co1; q++) {
                int e = selist[q];
                float4 tt = sT[e];
                float4 rho;
                rho.x = fminf(fmaxf(__fdividef(p.x, tt.x), -0.999999f), 0.999999f);
                rho.y = fminf(fmaxf(__fdividef(p.y, tt.y), -0.999999f), 0.999999f);
                rho.z = fminf(fmaxf(__fdividef(p.z, tt.z), -0.999999f), 0.999999f);
                rho.w = fminf(fmaxf(__fdividef(p.w, tt.w), -0.999999f), 0.999999f);
                sT[e] = rho;
            }
        }
        __syncthreads();
        if (it < NITER_ - 1) {
            // variables: vtot via log-product, T = tanh(vtot/2), messages
            // via addition formula. sT[e]: rho (in) -> tanh(m_vc) (out).
            if (t < K_) {
                const int n = t;
                float4 r0 = sT[3 * n], r1 = sT[3 * n + 1], r2 = sT[3 * n + 2];
                float4 l = sL[n];
                float Tx = tanh_clip_half(vtot_logprod(l.x, r0.x, r1.x, r2.x) * 0.5f);
                float Ty = tanh_clip_half(vtot_logprod(l.y, r0.y, r1.y, r2.y) * 0.5f);
                float Tz = tanh_clip_half(vtot_logprod(l.z, r0.z, r1.z, r2.z) * 0.5f);
                float Tw = tanh_clip_half(vtot_logprod(l.w, r0.w, r1.w, r2.w) * 0.5f);
                sT[3 * n    ] = make_float4(vc_msg(Tx, r0.x), vc_msg(Ty, r0.y), vc_msg(Tz, r0.z), vc_msg(Tw, r0.w));
                sT[3 * n + 1] = make_float4(vc_msg(Tx, r1.x), vc_msg(Ty, r1.y), vc_msg(Tz, r1.z), vc_msg(Tw, r1.w));
                sT[3 * n + 2] = make_float4(vc_msg(Tx, r2.x), vc_msg(Ty, r2.y), vc_msg(Tz, r2.z), vc_msg(Tw, r2.w));
            }
            __syncthreads();
        }
    }
    __syncthreads();

    // final hard decision: vtot from final rho (sign only)
    float* oh = out_bhat + (size_t)b * NUE_ * K_;
    if (t < K_) {
        const int n = t;
        float4 r0 = sT[3 * n], r1 = sT[3 * n + 1], r2 = sT[3 * n + 2];
        float4 l = sL[n];
        oh[0 * K_ + n] = (vtot_logprod(l.x, r0.x, r1.x, r2.x) < 0.f) ? 1.0f : 0.0f;
        oh[1 * K_ + n] = (vtot_logprod(l.y, r0.y, r1.y, r2.y) < 0.f) ? 1.0f : 0.0f;
        oh[2 * K_ + n] = (vtot_logprod(l.z, r0.z, r1.z, r2.z) < 0.f) ? 1.0f : 0.0f;
        oh[3 * K_ + n] = (vtot_logprod(l.w, r0.w, r1.w, r2.w) < 0.f) ? 1.0f : 0.0f;
    }
}

// ---------------------------------------------------------------------------
extern "C" void kernel_launch(void* const* d_in, const int* in_sizes, int n_in,
                              void* d_out, int out_size) {
    int shift = 10 - n_in;
    const float* ebno = (const float*)d_in[1 - shift];
    const int*   b    = (const int*)  d_in[2 - shift];
    const int*   cn   = (const int*)  d_in[4 - shift];
    const float* h_re = (const float*)d_in[6 - shift];
    const float* h_im = (const float*)d_in[7 - shift];
    const float* n_re = (const float*)d_in[8 - shift];
    const float* n_im = (const float*)d_in[9 - shift];

    float* out_bf = (float*)d_out;                       // (batch, NUE, K)
    float* out_bh = (float*)d_out + BATCH * NUE_ * K_;   // (batch, NUE, K)

    cudaFuncSetAttribute(decode_kernel, cudaFuncAttributeMaxDynamicSharedMemorySize, DEC_SMEM);

    enc_lmmse_kernel<<<BATCH, 256>>>(b, cn,
                                     (const float4*)h_re, (const float4*)h_im,
                                     (const float4*)n_re, (const float4*)n_im,
                                     ebno, out_bf);
    decode_kernel<<<BATCH, 512, DEC_SMEM>>>(out_bh);
}

// round 9
// speedup vs baseline: 2.3768x; 1.2611x over previous
#include <cuda_runtime.h>

// Problem constants (fixed by reference)
#define BATCH   1000
#define NUE_    4
#define K_      500
#define M_      500
#define N_      1000
#define NSYM_   250
#define NEDGE_  2000
#define NINFOE_ 1500
#define NITER_  5

// Static scratch
__device__ float g_llr[BATCH * NUE_ * N_];   // channel LLRs
__device__ short g_eoff[M_ + 1];
__device__ short g_elist[NINFOE_];

// ---------------------------------------------------------------------------
// Transcendentals (hybrid tanh + logprod validated R3-R8: rel_err 0.0).
// ---------------------------------------------------------------------------
__device__ __forceinline__ float tanh_clip_half(float x) {
    x = fminf(fmaxf(x, -9.9f), 9.9f);
    float ax = fabsf(x);
    float x2 = x * x;
    float num = x * fmaf(x2, fmaf(x2, 1.0f, 105.0f), 945.0f);
    float den = fmaf(x2, fmaf(x2, 15.0f, 420.0f), 945.0f);
    float tp  = __fdividef(num, den);
    float e   = __expf(2.0f * ax);
    float te  = copysignf(1.0f - __fdividef(2.0f, e + 1.0f), x);
    float t   = (ax < 1.0f) ? tp : te;
    return (t >= 0.f) ? fmaxf(t, 1e-7f) : fminf(t, -1e-7f);
}

// vtot = L + 2*atanh(r0)+2*atanh(r1)+2*atanh(r2)
//      = L + log(Prod(1+ri)/Prod(1-ri))   (ri pre-clipped; den >= 1e-18)
__device__ __forceinline__ float vtot_logprod(float L, float r0, float r1, float r2) {
    float num = (1.0f + r0) * (1.0f + r1) * (1.0f + r2);
    float den = (1.0f - r0) * (1.0f - r1) * (1.0f - r2);
    return L + __logf(__fdividef(num, den));
}

// v->c message via tanh addition formula: tanh((vt-c)/2) = (T - r)/(1 - T r)
__device__ __forceinline__ float vc_msg(float T, float r) {
    float t = __fdividef(T - r, fmaf(-T, r, 1.0f));
    return (t >= 0.f) ? fmaxf(t, 1e-7f) : fminf(t, -1e-7f);
}

__device__ __forceinline__ float clip999(float x) {
    return fminf(fmaxf(x, -0.999999f), 0.999999f);
}

// ---------------------------------------------------------------------------
// Fused encode + LMMSE. Block 0 additionally builds the check-node CSR
// (consumed only by the decode kernel) — hidden inside the wave structure.
// Parity via shared atomicXor over the raw cn edge list.
// ---------------------------------------------------------------------------
__global__ __launch_bounds__(256)
void enc_lmmse_kernel(const int* __restrict__ bin,
                      const int* __restrict__ cn,
                      const float4* __restrict__ hre4, const float4* __restrict__ him4,
                      const float4* __restrict__ nre4, const float4* __restrict__ nim4,
                      const float* __restrict__ ebno,
                      float* __restrict__ out_bf)
{
    __shared__ char scratch[12032];
    unsigned char* bits = (unsigned char*)scratch;      // [NUE_*N_] = 4000
    int* sp = (int*)(scratch + 4000);                   // [NUE_*M_] = 8000

    const int b = blockIdx.x;
    const int t = threadIdx.x;
    const int lane = t & 31, wid = t >> 5;

    // ---- block 0 only: build global CSR (aliases scratch; before bits) ----
    if (b == 0) {
        int*   cnt  = (int*)scratch;            // [M_]   2000
        int*   base = (int*)(scratch + 2000);   // [M_]   2000
        int*   wsum = (int*)(scratch + 4000);   // [8]      32
        short* sel  = (short*)(scratch + 4032); // [NINFOE_] 3000

        for (int m = t; m < M_; m += 256) cnt[m] = 0;
        __syncthreads();
        for (int e = t; e < NINFOE_; e += 256) atomicAdd(&cnt[cn[e]], 1);
        __syncthreads();
        int v0 = (2 * t     < M_) ? cnt[2 * t]     : 0;
        int v1 = (2 * t + 1 < M_) ? cnt[2 * t + 1] : 0;
        int s = v0 + v1, x = s;
#pragma unroll
        for (int d = 1; d < 32; d <<= 1) {
            int nn = __shfl_up_sync(0xffffffffu, x, d);
            if (lane >= d) x += nn;
        }
        if (lane == 31) wsum[wid] = x;
        __syncthreads();
        if (wid == 0) {
            int s2 = (lane < 8) ? wsum[lane] : 0;
#pragma unroll
            for (int d = 1; d < 8; d <<= 1) {
                int nn = __shfl_up_sync(0xffffffffu, s2, d);
                if (lane >= d) s2 += nn;
            }
            if (lane < 8) wsum[lane] = s2;
        }
        __syncthreads();
        int ex = x + ((wid > 0) ? wsum[wid - 1] : 0) - s;
        if (2 * t     < M_) { base[2 * t]     = ex;      g_eoff[2 * t]     = (short)ex; }
        if (2 * t + 1 < M_) { base[2 * t + 1] = ex + v0; g_eoff[2 * t + 1] = (short)(ex + v0); }
        if (t == 0) g_eoff[M_] = (short)NINFOE_;
        __syncthreads();
        for (int m = t; m < M_; m += 256) cnt[m] = 0;
        __syncthreads();
        for (int e = t; e < NINFOE_; e += 256) {
            int c = cn[e];
            int sl = atomicAdd(&cnt[c], 1);
            sel[base[c] + sl] = (short)e;
        }
        __syncthreads();
        for (int m = t; m < M_; m += 256) {
            int o0 = base[m], o1 = o0 + cnt[m];
            for (int i = o0 + 1; i < o1; i++) {
                short vv = sel[i];
                int j = i - 1;
                while (j >= o0 && sel[j] > vv) { sel[j + 1] = sel[j]; j--; }
                sel[j + 1] = vv;
            }
        }
        __syncthreads();
        for (int e = t; e < NINFOE_; e += 256) g_elist[e] = sel[e];
        __syncthreads();
    }

    // ---- stage info bits, emit bf output, zero parity accumulators ----
    const int* bb = bin + (size_t)b * NUE_ * K_;
    float* of = out_bf + (size_t)b * NUE_ * K_;
    for (int i = t; i < NUE_ * K_; i += 256) {
        int ue = i / K_, n = i - ue * K_;
        int bit = bb[i];
        bits[ue * N_ + n] = (unsigned char)bit;
        of[i] = (float)bit;
    }
    for (int i = t; i < NUE_ * M_; i += 256) sp[i] = 0;
    __syncthreads();

    // ---- parity via atomicXor over info edges (vn[e] = e/3 analytically) ----
    for (int e = t; e < NINFOE_; e += 256) {
        int c = cn[e], v = e / 3;
#pragma unroll
        for (int ue = 0; ue < 4; ue++)
            if (bits[ue * N_ + v]) atomicXor(&sp[ue * M_ + c], 1);
    }
    __syncthreads();
    for (int i = t; i < NUE_ * M_; i += 256) {
        int ue = i / M_, m = i - ue * M_;
        bits[ue * N_ + K_ + m] = (unsigned char)sp[i];
    }
    __syncthreads();

    if (t >= NSYM_) return;

    const float no  = 1.0f / (exp10f(ebno[0] * 0.1f) * 2.0f);
    const int r = b * NSYM_ + t;
    const float is2 = 0.70710678118654752440f;
    const float s10 = 0.31622776601683794f;

    float hr[4][4], hi[4][4];
#pragma unroll
    for (int i = 0; i < 4; i++) {
        float4 vr = hre4[r * 4 + i];
        float4 vi = him4[r * 4 + i];
        hr[i][0] = vr.x * is2; hr[i][1] = vr.y * is2; hr[i][2] = vr.z * is2; hr[i][3] = vr.w * is2;
        hi[i][0] = vi.x * is2; hi[i][1] = vi.y * is2; hi[i][2] = vi.z * is2; hi[i][3] = vi.w * is2;
    }

    float xr[4], xi[4];
#pragma unroll
    for (int j = 0; j < 4; j++) {
        uchar4 cb = *(const uchar4*)&bits[j * N_ + 4 * t];
        xr[j] = (float)((1 - 2 * (int)cb.x) * (1 + 2 * (int)cb.z)) * s10;
        xi[j] = (float)((1 - 2 * (int)cb.y) * (1 + 2 * (int)cb.w)) * s10;
    }

    const float ns = sqrtf(no * 0.5f);
    float4 wr4 = nre4[r], wi4 = nim4[r];
    float yr[4] = {wr4.x * ns, wr4.y * ns, wr4.z * ns, wr4.w * ns};
    float yi[4] = {wi4.x * ns, wi4.y * ns, wi4.z * ns, wi4.w * ns};
#pragma unroll
    for (int i = 0; i < 4; i++)
#pragma unroll
        for (int j = 0; j < 4; j++) {
            yr[i] += hr[i][j] * xr[j] - hi[i][j] * xi[j];
            yi[i] += hr[i][j] * xi[j] + hi[i][j] * xr[j];
        }

    float rr[4], ri[4];
#pragma unroll
    for (int j = 0; j < 4; j++) {
        float ar = 0.f, ai = 0.f;
#pragma unroll
        for (int i = 0; i < 4; i++) {
            ar += hr[i][j] * yr[i] + hi[i][j] * yi[i];
            ai += hr[i][j] * yi[i] - hi[i][j] * yr[i];
        }
        rr[j] = ar; ri[j] = ai;
    }

    float Br[4][4], Bi[4][4];
#pragma unroll
    for (int j = 0; j < 4; j++)
#pragma unroll
        for (int k = 0; k < 4; k++) {
            if (k > j) continue;
            float ar = (j == k) ? no : 0.f;
            float ai = 0.f;
#pragma unroll
            for (int i = 0; i < 4; i++) {
                ar += hr[i][j] * hr[i][k] + hi[i][j] * hi[i][k];
                ai += hr[i][j] * hi[i][k] - hi[i][j] * hr[i][k];
            }
            Br[j][k] = ar; Bi[j][k] = ai;
        }

    float rk[4];
#pragma unroll
    for (int k = 0; k < 4; k++) {
        float v = Br[k][k];
#pragma unroll
        for (int j = 0; j < 4; j++)
            if (j < k) v -= Br[k][j] * Br[k][j] + Bi[k][j] * Bi[k][j];
        float inv = rsqrtf(v);
        rk[k] = inv;
#pragma unroll
        for (int i = 0; i < 4; i++) {
            if (i <= k) continue;
            float cr = Br[i][k], ci = Bi[i][k];
#pragma unroll
            for (int j = 0; j < 4; j++)
                if (j < k) {
                    cr -= Br[i][j] * Br[k][j] + Bi[i][j] * Bi[k][j];
                    ci -= Bi[i][j] * Br[k][j] - Br[i][j] * Bi[k][j];
                }
            Br[i][k] = cr * inv; Bi[i][k] = ci * inv;
        }
    }

    float vr_[4], vi_[4];
#pragma unroll
    for (int i = 0; i < 4; i++) {
        float ar = rr[i], ai = ri[i];
#pragma unroll
        for (int j = 0; j < 4; j++)
            if (j < i) {
                ar -= Br[i][j] * vr_[j] - Bi[i][j] * vi_[j];
                ai -= Br[i][j] * vi_[j] + Bi[i][j] * vr_[j];
            }
        vr_[i] = ar * rk[i]; vi_[i] = ai * rk[i];
    }
    float xrw[4], xiw[4];
#pragma unroll
    for (int ii = 0; ii < 4; ii++) {
        int i = 3 - ii;
        float ar = vr_[i], ai = vi_[i];
#pragma unroll
        for (int j = 0; j < 4; j++)
            if (j > i) {
                ar -= Br[j][i] * xrw[j] + Bi[j][i] * xiw[j];
                ai -= Br[j][i] * xiw[j] - Bi[j][i] * xrw[j];
            }
        xrw[i] = ar * rk[i]; xiw[i] = ai * rk[i];
    }

    float dj[4];
#pragma unroll
    for (int j = 0; j < 4; j++) {
        float wr[4], wi[4];
#pragma unroll
        for (int i = 0; i < 4; i++) { wr[i] = 0.f; wi[i] = 0.f; }
        wr[j] = rk[j];
        float acc = rk[j] * rk[j];
#pragma unroll
        for (int i = 0; i < 4; i++) {
            if (i <= j) continue;
            float sr = 0.f, si = 0.f;
#pragma unroll
            for (int q = 0; q < 4; q++)
                if (q >= j && q < i) {
                    sr += Br[i][q] * wr[q] - Bi[i][q] * wi[q];
                    si += Br[i][q] * wi[q] + Bi[i][q] * wr[q];
                }
            wr[i] = -sr * rk[i]; wi[i] = -si * rk[i];
            acc += wr[i] * wr[i] + wi[i] * wi[i];
        }
        dj[j] = acc;
    }

#pragma unroll
    for (int c = 0; c < 4; c++) {
        float d = 1.0f - no * dj[c];
        float invd = 1.0f / d;
        float xhr = xrw[c] * invd, xhi = xiw[c] * invd;
        float noeff = fmaxf(invd - 1.0f, 1e-12f);
        float inoe = 1.0f / noeff;

        float a1  = xhr - s10,  a3  = xhr - 3.f * s10;
        float am1 = xhr + s10,  am3 = xhr + 3.f * s10;
        float f1 = -(a1 * a1), f3 = -(a3 * a3), fm1 = -(am1 * am1), fm3 = -(am3 * am3);
        float g1_ = xhi - s10,  g3_ = xhi - 3.f * s10;
        float gm1_ = xhi + s10, gm3_ = xhi + 3.f * s10;
        float g1 = -(g1_ * g1_), g3 = -(g3_ * g3_), gm1 = -(gm1_ * gm1_), gm3 = -(gm3_ * gm3_);

        float4 out = make_float4((fmaxf(f1, f3)  - fmaxf(fm1, fm3)) * inoe,
                                 (fmaxf(g1, g3)  - fmaxf(gm1, gm3)) * inoe,
                                 (fmaxf(f1, fm1) - fmaxf(f3, fm3))  * inoe,
                                 (fmaxf(g1, gm1) - fmaxf(g3, gm3))  * inoe);
        *(float4*)&g_llr[(size_t)(b * NUE_ + c) * N_ + 4 * t] = out;
    }
}

// ---------------------------------------------------------------------------
// Decoder: one block per batch element, 4 codewords as float4 lanes, 512 thr.
// Check phase stores ONLY its full product p_c (1 STS); the variable phase
// derives rho_i = clip(p/t_i) from its own previous message t_i. Same values,
// same ops as R8 — divisions moved to uniform variable threads, rho
// write+re-read round-trip eliminated.
// ---------------------------------------------------------------------------
extern __shared__ unsigned char dynsmem[];
#define DEC_SMEM (24000 + 8000 + 8000 + 8000 + 3000)

__global__ __launch_bounds__(512, 4)
void decode_kernel(const int* __restrict__ cn, float* __restrict__ out_bhat) {
    float4* sT  = (float4*)dynsmem;          // [NINFOE_] v->c message tanh
    float4* sP  = sT + NINFOE_;              // [M_]  check products
    float4* sTp = sP + M_;                   // [M_]  parity-edge tanh (invariant)
    float4* sLK = sTp + M_;                  // [K_]  info Lch
    short* selist = (short*)(sLK + K_);      // [NINFOE_]

    const int b = blockIdx.x;
    const int t = threadIdx.x;
    const float* Lb = g_llr + (size_t)b * NUE_ * N_;

    for (int e = t; e < NINFOE_; e += 512) selist[e] = g_elist[e];

    int c0 = 0, c1 = 0, c2 = 0, co0 = 0, co1 = 0;
    if (t < K_) {
        float4 l;
        l.x = Lb[0 * N_ + t]; l.y = Lb[1 * N_ + t];
        l.z = Lb[2 * N_ + t]; l.w = Lb[3 * N_ + t];
        sLK[t] = l;
        c0 = cn[3 * t]; c1 = cn[3 * t + 1]; c2 = cn[3 * t + 2];
        float4 m;
        m.x = tanh_clip_half(l.x * 0.5f);
        m.y = tanh_clip_half(l.y * 0.5f);
        m.z = tanh_clip_half(l.z * 0.5f);
        m.w = tanh_clip_half(l.w * 0.5f);
        sT[3 * t] = m; sT[3 * t + 1] = m; sT[3 * t + 2] = m;
    }
    if (t < M_) {
        float4 lp;
        lp.x = Lb[0 * N_ + K_ + t]; lp.y = Lb[1 * N_ + K_ + t];
        lp.z = Lb[2 * N_ + K_ + t]; lp.w = Lb[3 * N_ + K_ + t];
        float4 tp;
        tp.x = tanh_clip_half(lp.x * 0.5f);
        tp.y = tanh_clip_half(lp.y * 0.5f);
        tp.z = tanh_clip_half(lp.z * 0.5f);
        tp.w = tanh_clip_half(lp.w * 0.5f);
        sTp[t] = tp;
        co0 = g_eoff[t]; co1 = g_eoff[t + 1];
    }
    __syncthreads();

    float* oh = out_bhat + (size_t)b * NUE_ * K_;

    for (int it = 0; it < NITER_; it++) {
        // check phase: product over info edges (ascending) * parity tanh
        if (t < M_) {
            float4 p = sTp[t];
            for (int q = co0; q < co1; q++) {
                float4 tt = sT[selist[q]];
                p.x *= tt.x; p.y *= tt.y; p.z *= tt.z; p.w *= tt.w;
            }
            sP[t] = p;
        }
        __syncthreads();
        // variable phase: rho_i = clip(p_c / own t_i); then either new
        // messages (via logprod vtot + addition formula) or final decision.
        if (t < K_) {
            float4 m0 = sT[3 * t], p0 = sP[c0];
            float4 r0;
            r0.x = clip999(__fdividef(p0.x, m0.x));
            r0.y = clip999(__fdividef(p0.y, m0.y));
            r0.z = clip999(__fdividef(p0.z, m0.z));
            r0.w = clip999(__fdividef(p0.w, m0.w));
            float4 m1 = sT[3 * t + 1], p1 = sP[c1];
            float4 r1;
            r1.x = clip999(__fdividef(p1.x, m1.x));
            r1.y = clip999(__fdividef(p1.y, m1.y));
            r1.z = clip999(__fdividef(p1.z, m1.z));
            r1.w = clip999(__fdividef(p1.w, m1.w));
            float4 m2 = sT[3 * t + 2], p2 = sP[c2];
            float4 r2;
            r2.x = clip999(__fdividef(p2.x, m2.x));
            r2.y = clip999(__fdividef(p2.y, m2.y));
            r2.z = clip999(__fdividef(p2.z, m2.z));
            r2.w = clip999(__fdividef(p2.w, m2.w));
            float4 l = sLK[t];
            if (it < NITER_ - 1) {
                float Tx = tanh_clip_half(vtot_logprod(l.x, r0.x, r1.x, r2.x) * 0.5f);
                float Ty = tanh_clip_half(vtot_logprod(l.y, r0.y, r1.y, r2.y) * 0.5f);
                float Tz = tanh_clip_half(vtot_logprod(l.z, r0.z, r1.z, r2.z) * 0.5f);
                float Tw = tanh_clip_half(vtot_logprod(l.w, r0.w, r1.w, r2.w) * 0.5f);
                sT[3 * t    ] = make_float4(vc_msg(Tx, r0.x), vc_msg(Ty, r0.y), vc_msg(Tz, r0.z), vc_msg(Tw, r0.w));
                sT[3 * t + 1] = make_float4(vc_msg(Tx, r1.x), vc_msg(Ty, r1.y), vc_msg(Tz, r1.z), vc_msg(Tw, r1.w));
                sT[3 * t + 2] = make_float4(vc_msg(Tx, r2.x), vc_msg(Ty, r2.y), vc_msg(Tz, r2.z), vc_msg(Tw, r2.w));
            } else {
                oh[0 * K_ + t] = (vtot_logprod(l.x, r0.x, r1.x, r2.x) < 0.f) ? 1.0f : 0.0f;
                oh[1 * K_ + t] = (vtot_logprod(l.y, r0.y, r1.y, r2.y) < 0.f) ? 1.0f : 0.0f;
                oh[2 * K_ + t] = (vtot_logprod(l.z, r0.z, r1.z, r2.z) < 0.f) ? 1.0f : 0.0f;
                oh[3 * K_ + t] = (vtot_logprod(l.w, r0.w, r1.w, r2.w) < 0.f) ? 1.0f : 0.0f;
            }
        }
        if (it < NITER_ - 1) __syncthreads();
    }
}

// ---------------------------------------------------------------------------
extern "C" void kernel_launch(void* const* d_in, const int* in_sizes, int n_in,
                              void* d_out, int out_size) {
    int shift = 10 - n_in;
    const float* ebno = (const float*)d_in[1 - shift];
    const int*   b    = (const int*)  d_in[2 - shift];
    const int*   cn   = (const int*)  d_in[4 - shift];
    const float* h_re = (const float*)d_in[6 - shift];
    const float* h_im = (const float*)d_in[7 - shift];
    const float* n_re = (const float*)d_in[8 - shift];
    const float* n_im = (const float*)d_in[9 - shift];

    float* out_bf = (float*)d_out;                       // (batch, NUE, K)
    float* out_bh = (float*)d_out + BATCH * NUE_ * K_;   // (batch, NUE, K)

    cudaFuncSetAttribute(decode_kernel, cudaFuncAttributeMaxDynamicSharedMemorySize, DEC_SMEM);

    enc_lmmse_kernel<<<BATCH, 256>>>(b, cn,
                                     (const float4*)h_re, (const float4*)h_im,
                                     (const float4*)n_re, (const float4*)n_im,
                                     ebno, out_bf);
    decode_kernel<<<BATCH, 512, DEC_SMEM>>>(cn, out_bh);
}

// round 10
// speedup vs baseline: 2.5784x; 1.0848x over previous
#include <cuda_runtime.h>

// Problem constants (fixed by reference)
#define BATCH   1000
#define NUE_    4
#define K_      500
#define M_      500
#define N_      1000
#define NSYM_   250
#define NEDGE_  2000
#define NINFOE_ 1500
#define NITER_  5

// Static scratch
__device__ float g_llr[BATCH * NUE_ * N_];   // channel LLRs
__device__ short g_eoff[M_ + 1];
__device__ short g_elist[NINFOE_];

// ---------------------------------------------------------------------------
// Hybrid tanh (validated R3-R9) — used only at init now.
// ---------------------------------------------------------------------------
__device__ __forceinline__ float tanh_clip_half(float x) {
    x = fminf(fmaxf(x, -9.9f), 9.9f);
    float ax = fabsf(x);
    float x2 = x * x;
    float num = x * fmaf(x2, fmaf(x2, 1.0f, 105.0f), 945.0f);
    float den = fmaf(x2, fmaf(x2, 15.0f, 420.0f), 945.0f);
    float tp  = __fdividef(num, den);
    float e   = __expf(2.0f * ax);
    float te  = copysignf(1.0f - __fdividef(2.0f, e + 1.0f), x);
    float t   = (ax < 1.0f) ? tp : te;
    return (t >= 0.f) ? fmaxf(t, 1e-7f) : fminf(t, -1e-7f);
}

// v->c message via tanh addition formula: tanh((vt-c)/2) = (T - r)/(1 - T r)
__device__ __forceinline__ float vc_msg(float T, float r) {
    float t = __fdividef(T - r, fmaf(-T, r, 1.0f));
    return (t >= 0.f) ? fmaxf(t, 1e-7f) : fminf(t, -1e-7f);
}

__device__ __forceinline__ float clip999(float x) {
    return fminf(fmaxf(x, -0.999999f), 0.999999f);
}

// Q = Prod(1+ri)/Prod(1-ri)  (ri pre-clipped => num,den in [1e-18, 8])
__device__ __forceinline__ float qratio(float r0, float r1, float r2) {
    float num = (1.0f + r0) * (1.0f + r1) * (1.0f + r2);
    float den = (1.0f - r0) * (1.0f - r1) * (1.0f - r2);
    return __fdividef(num, den);
}

// T = tanh(vtot/2) with e^vtot = eL * Q  (exact in saturation; abs err ~5e-7
// in vt-domain, below the validated __logf-cancellation error of R8/R9)
__device__ __forceinline__ float t_from_E(float E) {
    return 1.0f - __fdividef(2.0f, E + 1.0f);
}

// ---------------------------------------------------------------------------
// Fused encode + LMMSE. Block 0 additionally builds the check-node CSR
// (consumed only by the decode kernel) — hidden inside the wave structure.
// Parity via shared atomicXor over the raw cn edge list.
// ---------------------------------------------------------------------------
__global__ __launch_bounds__(256)
void enc_lmmse_kernel(const int* __restrict__ bin,
                      const int* __restrict__ cn,
                      const float4* __restrict__ hre4, const float4* __restrict__ him4,
                      const float4* __restrict__ nre4, const float4* __restrict__ nim4,
                      const float* __restrict__ ebno,
                      float* __restrict__ out_bf)
{
    __shared__ char scratch[12032];
    unsigned char* bits = (unsigned char*)scratch;      // [NUE_*N_] = 4000
    int* sp = (int*)(scratch + 4000);                   // [NUE_*M_] = 8000

    const int b = blockIdx.x;
    const int t = threadIdx.x;
    const int lane = t & 31, wid = t >> 5;

    // ---- block 0 only: build global CSR (aliases scratch; before bits) ----
    if (b == 0) {
        int*   cnt  = (int*)scratch;            // [M_]   2000
        int*   base = (int*)(scratch + 2000);   // [M_]   2000
        int*   wsum = (int*)(scratch + 4000);   // [8]      32
        short* sel  = (short*)(scratch + 4032); // [NINFOE_] 3000

        for (int m = t; m < M_; m += 256) cnt[m] = 0;
        __syncthreads();
        for (int e = t; e < NINFOE_; e += 256) atomicAdd(&cnt[cn[e]], 1);
        __syncthreads();
        int v0 = (2 * t     < M_) ? cnt[2 * t]     : 0;
        int v1 = (2 * t + 1 < M_) ? cnt[2 * t + 1] : 0;
        int s = v0 + v1, x = s;
#pragma unroll
        for (int d = 1; d < 32; d <<= 1) {
            int nn = __shfl_up_sync(0xffffffffu, x, d);
            if (lane >= d) x += nn;
        }
        if (lane == 31) wsum[wid] = x;
        __syncthreads();
        if (wid == 0) {
            int s2 = (lane < 8) ? wsum[lane] : 0;
#pragma unroll
            for (int d = 1; d < 8; d <<= 1) {
                int nn = __shfl_up_sync(0xffffffffu, s2, d);
                if (lane >= d) s2 += nn;
            }
            if (lane < 8) wsum[lane] = s2;
        }
        __syncthreads();
        int ex = x + ((wid > 0) ? wsum[wid - 1] : 0) - s;
        if (2 * t     < M_) { base[2 * t]     = ex;      g_eoff[2 * t]     = (short)ex; }
        if (2 * t + 1 < M_) { base[2 * t + 1] = ex + v0; g_eoff[2 * t + 1] = (short)(ex + v0); }
        if (t == 0) g_eoff[M_] = (short)NINFOE_;
        __syncthreads();
        for (int m = t; m < M_; m += 256) cnt[m] = 0;
        __syncthreads();
        for (int e = t; e < NINFOE_; e += 256) {
            int c = cn[e];
            int sl = atomicAdd(&cnt[c], 1);
            sel[base[c] + sl] = (short)e;
        }
        __syncthreads();
        for (int m = t; m < M_; m += 256) {
            int o0 = base[m], o1 = o0 + cnt[m];
            for (int i = o0 + 1; i < o1; i++) {
                short vv = sel[i];
                int j = i - 1;
                while (j >= o0 && sel[j] > vv) { sel[j + 1] = sel[j]; j--; }
                sel[j + 1] = vv;
            }
        }
        __syncthreads();
        for (int e = t; e < NINFOE_; e += 256) g_elist[e] = sel[e];
        __syncthreads();
    }

    // ---- stage info bits, emit bf output, zero parity accumulators ----
    const int* bb = bin + (size_t)b * NUE_ * K_;
    float* of = out_bf + (size_t)b * NUE_ * K_;
    for (int i = t; i < NUE_ * K_; i += 256) {
        int ue = i / K_, n = i - ue * K_;
        int bit = bb[i];
        bits[ue * N_ + n] = (unsigned char)bit;
        of[i] = (float)bit;
    }
    for (int i = t; i < NUE_ * M_; i += 256) sp[i] = 0;
    __syncthreads();

    // ---- parity via atomicXor over info edges (vn[e] = e/3 analytically) ----
    for (int e = t; e < NINFOE_; e += 256) {
        int c = cn[e], v = e / 3;
#pragma unroll
        for (int ue = 0; ue < 4; ue++)
            if (bits[ue * N_ + v]) atomicXor(&sp[ue * M_ + c], 1);
    }
    __syncthreads();
    for (int i = t; i < NUE_ * M_; i += 256) {
        int ue = i / M_, m = i - ue * M_;
        bits[ue * N_ + K_ + m] = (unsigned char)sp[i];
    }
    __syncthreads();

    if (t >= NSYM_) return;

    const float no  = 1.0f / (exp10f(ebno[0] * 0.1f) * 2.0f);
    const int r = b * NSYM_ + t;
    const float is2 = 0.70710678118654752440f;
    const float s10 = 0.31622776601683794f;

    float hr[4][4], hi[4][4];
#pragma unroll
    for (int i = 0; i < 4; i++) {
        float4 vr = hre4[r * 4 + i];
        float4 vi = him4[r * 4 + i];
        hr[i][0] = vr.x * is2; hr[i][1] = vr.y * is2; hr[i][2] = vr.z * is2; hr[i][3] = vr.w * is2;
        hi[i][0] = vi.x * is2; hi[i][1] = vi.y * is2; hi[i][2] = vi.z * is2; hi[i][3] = vi.w * is2;
    }

    float xr[4], xi[4];
#pragma unroll
    for (int j = 0; j < 4; j++) {
        uchar4 cb = *(const uchar4*)&bits[j * N_ + 4 * t];
        xr[j] = (float)((1 - 2 * (int)cb.x) * (1 + 2 * (int)cb.z)) * s10;
        xi[j] = (float)((1 - 2 * (int)cb.y) * (1 + 2 * (int)cb.w)) * s10;
    }

    const float ns = sqrtf(no * 0.5f);
    float4 wr4 = nre4[r], wi4 = nim4[r];
    float yr[4] = {wr4.x * ns, wr4.y * ns, wr4.z * ns, wr4.w * ns};
    float yi[4] = {wi4.x * ns, wi4.y * ns, wi4.z * ns, wi4.w * ns};
#pragma unroll
    for (int i = 0; i < 4; i++)
#pragma unroll
        for (int j = 0; j < 4; j++) {
            yr[i] += hr[i][j] * xr[j] - hi[i][j] * xi[j];
            yi[i] += hr[i][j] * xi[j] + hi[i][j] * xr[j];
        }

    float rr[4], ri[4];
#pragma unroll
    for (int j = 0; j < 4; j++) {
        float ar = 0.f, ai = 0.f;
#pragma unroll
        for (int i = 0; i < 4; i++) {
            ar += hr[i][j] * yr[i] + hi[i][j] * yi[i];
            ai += hr[i][j] * yi[i] - hi[i][j] * yr[i];
        }
        rr[j] = ar; ri[j] = ai;
    }

    float Br[4][4], Bi[4][4];
#pragma unroll
    for (int j = 0; j < 4; j++)
#pragma unroll
        for (int k = 0; k < 4; k++) {
            if (k > j) continue;
            float ar = (j == k) ? no : 0.f;
            float ai = 0.f;
#pragma unroll
            for (int i = 0; i < 4; i++) {
                ar += hr[i][j] * hr[i][k] + hi[i][j] * hi[i][k];
                ai += hr[i][j] * hi[i][k] - hi[i][j] * hr[i][k];
            }
            Br[j][k] = ar; Bi[j][k] = ai;
        }

    float rk[4];
#pragma unroll
    for (int k = 0; k < 4; k++) {
        float v = Br[k][k];
#pragma unroll
        for (int j = 0; j < 4; j++)
            if (j < k) v -= Br[k][j] * Br[k][j] + Bi[k][j] * Bi[k][j];
        float inv = rsqrtf(v);
        rk[k] = inv;
#pragma unroll
        for (int i = 0; i < 4; i++) {
            if (i <= k) continue;
            float cr = Br[i][k], ci = Bi[i][k];
#pragma unroll
            for (int j = 0; j < 4; j++)
                if (j < k) {
                    cr -= Br[i][j] * Br[k][j] + Bi[i][j] * Bi[k][j];
                    ci -= Bi[i][j] * Br[k][j] - Br[i][j] * Bi[k][j];
                }
            Br[i][k] = cr * inv; Bi[i][k] = ci * inv;
        }
    }

    float vr_[4], vi_[4];
#pragma unroll
    for (int i = 0; i < 4; i++) {
        float ar = rr[i], ai = ri[i];
#pragma unroll
        for (int j = 0; j < 4; j++)
            if (j < i) {
                ar -= Br[i][j] * vr_[j] - Bi[i][j] * vi_[j];
                ai -= Br[i][j] * vi_[j] + Bi[i][j] * vr_[j];
            }
        vr_[i] = ar * rk[i]; vi_[i] = ai * rk[i];
    }
    float xrw[4], xiw[4];
#pragma unroll
    for (int ii = 0; ii < 4; ii++) {
        int i = 3 - ii;
        float ar = vr_[i], ai = vi_[i];
#pragma unroll
        for (int j = 0; j < 4; j++)
            if (j > i) {
                ar -= Br[j][i] * xrw[j] + Bi[j][i] * xiw[j];
                ai -= Br[j][i] * xiw[j] - Bi[j][i] * xrw[j];
            }
        xrw[i] = ar * rk[i]; xiw[i] = ai * rk[i];
    }

    float dj[4];
#pragma unroll
    for (int j = 0; j < 4; j++) {
        float wr[4], wi[4];
#pragma unroll
        for (int i = 0; i < 4; i++) { wr[i] = 0.f; wi[i] = 0.f; }
        wr[j] = rk[j];
        float acc = rk[j] * rk[j];
#pragma unroll
        for (int i = 0; i < 4; i++) {
            if (i <= j) continue;
            float sr = 0.f, si = 0.f;
#pragma unroll
            for (int q = 0; q < 4; q++)
                if (q >= j && q < i) {
                    sr += Br[i][q] * wr[q] - Bi[i][q] * wi[q];
                    si += Br[i][q] * wi[q] + Bi[i][q] * wr[q];
                }
            wr[i] = -sr * rk[i]; wi[i] = -si * rk[i];
            acc += wr[i] * wr[i] + wi[i] * wi[i];
        }
        dj[j] = acc;
    }

#pragma unroll
    for (int c = 0; c < 4; c++) {
        float d = 1.0f - no * dj[c];
        float invd = 1.0f / d;
        float xhr = xrw[c] * invd, xhi = xiw[c] * invd;
        float noeff = fmaxf(invd - 1.0f, 1e-12f);
        float inoe = 1.0f / noeff;

        float a1  = xhr - s10,  a3  = xhr - 3.f * s10;
        float am1 = xhr + s10,  am3 = xhr + 3.f * s10;
        float f1 = -(a1 * a1), f3 = -(a3 * a3), fm1 = -(am1 * am1), fm3 = -(am3 * am3);
        float g1_ = xhi - s10,  g3_ = xhi - 3.f * s10;
        float gm1_ = xhi + s10, gm3_ = xhi + 3.f * s10;
        float g1 = -(g1_ * g1_), g3 = -(g3_ * g3_), gm1 = -(gm1_ * gm1_), gm3 = -(gm3_ * gm3_);

        float4 out = make_float4((fmaxf(f1, f3)  - fmaxf(fm1, fm3)) * inoe,
                                 (fmaxf(g1, g3)  - fmaxf(gm1, gm3)) * inoe,
                                 (fmaxf(f1, fm1) - fmaxf(f3, fm3))  * inoe,
                                 (fmaxf(g1, gm1) - fmaxf(g3, gm3))  * inoe);
        *(float4*)&g_llr[(size_t)(b * NUE_ + c) * N_ + 4 * t] = out;
    }
}

// ---------------------------------------------------------------------------
// Decoder: one block per batch element, 4 codewords as float4 lanes, 512 thr.
// Check phase stores only its product p_c. Variable phase: rho = clip(p/t);
// T from E = e^L * Q (e^L precomputed; log+tanh eliminated from the loop);
// messages via tanh addition formula; final decision = (E < 1).
// ---------------------------------------------------------------------------
extern __shared__ unsigned char dynsmem[];
#define DEC_SMEM (24000 + 8000 + 8000 + 8000 + 3000)

__global__ __launch_bounds__(512, 4)
void decode_kernel(const int* __restrict__ cn, float* __restrict__ out_bhat) {
    float4* sT  = (float4*)dynsmem;          // [NINFOE_] v->c message tanh
    float4* sP  = sT + NINFOE_;              // [M_]  check products
    float4* sTp = sP + M_;                   // [M_]  parity-edge tanh (invariant)
    float4* sEL = sTp + M_;                  // [K_]  exp(Lch) per info var
    short* selist = (short*)(sEL + K_);      // [NINFOE_]

    const int b = blockIdx.x;
    const int t = threadIdx.x;
    const float* Lb = g_llr + (size_t)b * NUE_ * N_;

    for (int e = t; e < NINFOE_; e += 512) selist[e] = g_elist[e];

    int c0 = 0, c1 = 0, c2 = 0, co0 = 0, co1 = 0;
    if (t < K_) {
        float4 l;
        l.x = Lb[0 * N_ + t]; l.y = Lb[1 * N_ + t];
        l.z = Lb[2 * N_ + t]; l.w = Lb[3 * N_ + t];
        float4 el;
        el.x = __expf(l.x); el.y = __expf(l.y);
        el.z = __expf(l.z); el.w = __expf(l.w);
        sEL[t] = el;
        c0 = cn[3 * t]; c1 = cn[3 * t + 1]; c2 = cn[3 * t + 2];
        float4 m;
        m.x = tanh_clip_half(l.x * 0.5f);
        m.y = tanh_clip_half(l.y * 0.5f);
        m.z = tanh_clip_half(l.z * 0.5f);
        m.w = tanh_clip_half(l.w * 0.5f);
        sT[3 * t] = m; sT[3 * t + 1] = m; sT[3 * t + 2] = m;
    }
    if (t < M_) {
        float4 lp;
        lp.x = Lb[0 * N_ + K_ + t]; lp.y = Lb[1 * N_ + K_ + t];
        lp.z = Lb[2 * N_ + K_ + t]; lp.w = Lb[3 * N_ + K_ + t];
        float4 tp;
        tp.x = tanh_clip_half(lp.x * 0.5f);
        tp.y = tanh_clip_half(lp.y * 0.5f);
        tp.z = tanh_clip_half(lp.z * 0.5f);
        tp.w = tanh_clip_half(lp.w * 0.5f);
        sTp[t] = tp;
        co0 = g_eoff[t]; co1 = g_eoff[t + 1];
    }
    __syncthreads();

    float* oh = out_bhat + (size_t)b * NUE_ * K_;

    for (int it = 0; it < NITER_; it++) {
        // check phase: product over info edges * parity tanh -> sP
        if (t < M_) {
            float4 p = sTp[t];
            for (int q = co0; q < co1; q++) {
                float4 tt = sT[selist[q]];
                p.x *= tt.x; p.y *= tt.y; p.z *= tt.z; p.w *= tt.w;
            }
            sP[t] = p;
        }
        __syncthreads();
        // variable phase
        if (t < K_) {
            float4 m0 = sT[3 * t], p0 = sP[c0];
            float4 r0;
            r0.x = clip999(__fdividef(p0.x, m0.x));
            r0.y = clip999(__fdividef(p0.y, m0.y));
            r0.z = clip999(__fdividef(p0.z, m0.z));
            r0.w = clip999(__fdividef(p0.w, m0.w));
            float4 m1 = sT[3 * t + 1], p1 = sP[c1];
            float4 r1;
            r1.x = clip999(__fdividef(p1.x, m1.x));
            r1.y = clip999(__fdividef(p1.y, m1.y));
            r1.z = clip999(__fdividef(p1.z, m1.z));
            r1.w = clip999(__fdividef(p1.w, m1.w));
            float4 m2 = sT[3 * t + 2], p2 = sP[c2];
            float4 r2;
            r2.x = clip999(__fdividef(p2.x, m2.x));
            r2.y = clip999(__fdividef(p2.y, m2.y));
            r2.z = clip999(__fdividef(p2.z, m2.z));
            r2.w = clip999(__fdividef(p2.w, m2.w));
            float4 el = sEL[t];
            float Ex = el.x * qratio(r0.x, r1.x, r2.x);
            float Ey = el.y * qratio(r0.y, r1.y, r2.y);
            float Ez = el.z * qratio(r0.z, r1.z, r2.z);
            float Ew = el.w * qratio(r0.w, r1.w, r2.w);
            if (it < NITER_ - 1) {
                float Tx = t_from_E(Ex);
                float Ty = t_from_E(Ey);
                float Tz = t_from_E(Ez);
                float Tw = t_from_E(Ew);
                sT[3 * t    ] = make_float4(vc_msg(Tx, r0.x), vc_msg(Ty, r0.y), vc_msg(Tz, r0.z), vc_msg(Tw, r0.w));
                sT[3 * t + 1] = make_float4(vc_msg(Tx, r1.x), vc_msg(Ty, r1.y), vc_msg(Tz, r1.z), vc_msg(Tw, r1.w));
                sT[3 * t + 2] = make_float4(vc_msg(Tx, r2.x), vc_msg(Ty, r2.y), vc_msg(Tz, r2.z), vc_msg(Tw, r2.w));
            } else {
                oh[0 * K_ + t] = (Ex < 1.0f) ? 1.0f : 0.0f;
                oh[1 * K_ + t] = (Ey < 1.0f) ? 1.0f : 0.0f;
                oh[2 * K_ + t] = (Ez < 1.0f) ? 1.0f : 0.0f;
                oh[3 * K_ + t] = (Ew < 1.0f) ? 1.0f : 0.0f;
            }
        }
        if (it < NITER_ - 1) __syncthreads();
    }
}

// ---------------------------------------------------------------------------
extern "C" void kernel_launch(void* const* d_in, const int* in_sizes, int n_in,
                              void* d_out, int out_size) {
    int shift = 10 - n_in;
    const float* ebno = (const float*)d_in[1 - shift];
    const int*   b    = (const int*)  d_in[2 - shift];
    const int*   cn   = (const int*)  d_in[4 - shift];
    const float* h_re = (const float*)d_in[6 - shift];
    const float* h_im = (const float*)d_in[7 - shift];
    const float* n_re = (const float*)d_in[8 - shift];
    const float* n_im = (const float*)d_in[9 - shift];

    float* out_bf = (float*)d_out;                       // (batch, NUE, K)
    float* out_bh = (float*)d_out + BATCH * NUE_ * K_;   // (batch, NUE, K)

    cudaFuncSetAttribute(decode_kernel, cudaFuncAttributeMaxDynamicSharedMemorySize, DEC_SMEM);

    enc_lmmse_kernel<<<BATCH, 256>>>(b, cn,
                                     (const float4*)h_re, (const float4*)h_im,
                                     (const float4*)n_re, (const float4*)n_im,
                                     ebno, out_bf);
    decode_kernel<<<BATCH, 512, DEC_SMEM>>>(cn, out_bh);
}